// round 7
// baseline (speedup 1.0000x reference)
#include <cuda_runtime.h>
#include <cuda_fp16.h>
#include <math.h>
#include <stdint.h>

#define BB 4
#define TT 256
#define UU 64
#define DD 640
#define HH 640
#define VV 1024
#define MTOT (BB*TT*UU)   // 65536
#define L2E 1.4426950408889634f

#define AROW 648          // f16 units per A row in SMEM
#define BROW 24           // f16 units per B row in SMEM (16 + 8 pad)
#define BROWB 48          // bytes per B row
#define BBUF (256*BROWB)  // bytes per B stage = 12288
#define NSTEP 160         // 4 chunks x 40 k-steps

// ---- static device scratch ----
__device__ float  g_enc[BB*TT*HH];
__device__ float  g_pred[BB*UU*HH];
__device__ float  g_part[5*BB*TT*HH];
__device__ float  g_partp[5*BB*UU*HH];
__device__ __half g_w16t[VV*HH];                 // W_fc^T f16: [n][k]
__device__ __half g_joint[(size_t)MTOT*HH];      // tanh(enc+pred) f16
__device__ __half g_logits[(size_t)MTOT*VV];     // unnormalized logits f16

__device__ __forceinline__ uint32_t smem_u32(const void* p) {
    uint32_t a;
    asm("{ .reg .u64 t; cvta.to.shared.u64 t, %1; cvt.u32.u64 %0, t; }"
        : "=r"(a) : "l"(p));
    return a;
}
__device__ __forceinline__ void cpasync16(uint32_t dst, const void* src) {
    asm volatile("cp.async.ca.shared.global [%0], [%1], 16;" ::"r"(dst), "l"(src));
}
#define CP_COMMIT() asm volatile("cp.async.commit_group;")
#define CP_WAIT(n) asm volatile("cp.async.wait_group %0;" ::"n"(n))

__device__ __forceinline__ void ldsm_x4(uint32_t* r, uint32_t addr) {
    asm volatile("ldmatrix.sync.aligned.m8n8.x4.shared.b16 {%0,%1,%2,%3}, [%4];"
                 : "=r"(r[0]), "=r"(r[1]), "=r"(r[2]), "=r"(r[3]) : "r"(addr));
}
__device__ __forceinline__ float ex2sum2(float x0, float x1) {
    __half2 h = __floats2half2_rn(x0, x1);
    unsigned int u = *(unsigned int*)&h, o;
    asm("ex2.approx.f16x2 %0, %1;" : "=r"(o) : "r"(u));
    float2 f = __half22float2(*(__half2*)&o);
    return f.x + f.y;
}
__device__ __forceinline__ __half2 u2h2(uint32_t u) { return *(__half2*)&u; }

// ===========================================================================
// W_fc fp32 [k][n] -> f16 transposed [n][k]
// ===========================================================================
__global__ __launch_bounds__(256) void convert_wfc(const float* __restrict__ Wfc) {
    __shared__ float t[32][33];
    int n0 = blockIdx.x * 32, k0 = blockIdx.y * 32;
    int tx = threadIdx.x & 31, ty = threadIdx.x >> 5;
#pragma unroll
    for (int j = 0; j < 4; j++)
        t[ty + 8 * j][tx] = Wfc[(size_t)(k0 + ty + 8 * j) * VV + n0 + tx];
    __syncthreads();
#pragma unroll
    for (int j = 0; j < 4; j++)
        g_w16t[(size_t)(n0 + ty + 8 * j) * HH + k0 + tx] = __float2half(t[tx][ty + 8 * j]);
}

// ===========================================================================
// Projection GEMM (split-K by 5) + reduce
// ===========================================================================
__global__ __launch_bounds__(256) void proj_gemm(const float* __restrict__ X,
                                                 const float* __restrict__ W, int which) {
    float* C = which ? g_partp : g_part;
    const int Mrows = which ? (BB * UU) : (BB * TT);
    __shared__ float As[16][65];
    __shared__ float Bs[16][65];
    const int tid = threadIdx.x;
    const int bm = blockIdx.x * 64, bn = blockIdx.y * 64, kz = blockIdx.z;
    const int ty = tid / 16, tx = tid % 16;
    float c[4][4];
#pragma unroll
    for (int i = 0; i < 4; i++)
#pragma unroll
        for (int j = 0; j < 4; j++) c[i][j] = 0.f;
    for (int k0 = kz * 128; k0 < kz * 128 + 128; k0 += 16) {
        for (int l = tid; l < 64 * 16; l += 256) {
            int row = l >> 4, kk = l & 15;
            As[kk][row] = X[(size_t)(bm + row) * DD + k0 + kk];
        }
        for (int l = tid; l < 16 * 64; l += 256) {
            int kk = l >> 6, col = l & 63;
            Bs[kk][col] = W[(size_t)(k0 + kk) * HH + bn + col];
        }
        __syncthreads();
#pragma unroll
        for (int kk = 0; kk < 16; kk++) {
            float a[4], b[4];
#pragma unroll
            for (int i = 0; i < 4; i++) a[i] = As[kk][ty * 4 + i];
#pragma unroll
            for (int j = 0; j < 4; j++) b[j] = Bs[kk][tx * 4 + j];
#pragma unroll
            for (int i = 0; i < 4; i++)
#pragma unroll
                for (int j = 0; j < 4; j++) c[i][j] += a[i] * b[j];
        }
        __syncthreads();
    }
    float* Cz = C + (size_t)kz * Mrows * HH;
#pragma unroll
    for (int i = 0; i < 4; i++)
#pragma unroll
        for (int j = 0; j < 4; j++)
            Cz[(size_t)(bm + ty * 4 + i) * HH + bn + tx * 4 + j] = c[i][j];
}

__global__ __launch_bounds__(256) void proj_reduce(const float* __restrict__ b_enc,
                                                   const float* __restrict__ b_pred) {
    int idx = blockIdx.x * 256 + threadIdx.x;
    const int encN = BB * TT * HH, predN = BB * UU * HH;
    if (idx < encN) {
        float s = b_enc[idx % HH];
#pragma unroll
        for (int z = 0; z < 5; z++) s += g_part[(size_t)z * encN + idx];
        g_enc[idx] = s;
    } else {
        int j = idx - encN;
        if (j < predN) {
            float s = b_pred[j % HH];
#pragma unroll
            for (int z = 0; z < 5; z++) s += g_partp[(size_t)z * predN + j];
            g_pred[j] = s;
        }
    }
}

// ===========================================================================
// Joint tanh -> f16
// ===========================================================================
__global__ __launch_bounds__(256) void tanh_joint() {
    const int r0 = blockIdx.x * 32;
    const float* enc = g_enc + (size_t)(r0 / UU) * HH;
    const float* pred = g_pred + ((size_t)(r0 / (TT * UU)) * UU + (r0 % UU)) * HH;
    for (int p = threadIdx.x; p < 32 * (HH / 2); p += 256) {
        int i = p / (HH / 2);
        int h2 = p % (HH / 2);
        float2 e = *(const float2*)&enc[h2 * 2];
        float2 q = *(const float2*)&pred[(size_t)i * HH + h2 * 2];
        __half2 hx = __floats2half2_rn(e.x + q.x, e.y + q.y);
        unsigned int u = *(unsigned int*)&hx, o;
        asm("tanh.approx.f16x2 %0, %1;" : "=r"(o) : "r"(u));
        *(unsigned int*)&g_joint[(size_t)(r0 + i) * HH + h2 * 2] = o;
    }
}

// ===========================================================================
// Main kernel: HYBRID. Per 256-col chunk: cols 0..191 via mma.sync f16
// (8 warps, 6 nt each), cols 192..255 via SIMT HFMA2 k-pairs on the FMA pipe
// (each warp: its 64 rows x 16 cols, f16 partials promoted to f32 every 8
// k-steps). Same SMEM tiles feed both. One barrier per k-step.
// ===========================================================================
#define SM_A 0
#define SM_B (128 * AROW * 2)          // 165888
#define SM_RED (SM_B + 3 * BBUF)       // 202752 (tensor [4][128] + simt [4][128])
#define SM_SCM (SM_RED + 4096)         // 206848
#define SM_RMAX (SM_SCM + 512)
#define SM_RSUM (SM_RMAX + 512)
#define SM_TOTAL (SM_RSUM + 512)       // 208384

__global__ __launch_bounds__(256, 1) void joint_gemm(const float* __restrict__ bfc,
                                                     float* __restrict__ out) {
    extern __shared__ char smc[];
    const uint32_t sbase = smem_u32(smc);
    float* red = (float*)(smc + SM_RED);          // [4][128] tensor
    float* red2 = (float*)(smc + SM_RED + 2048);  // [4][128] simt
    float* scm = (float*)(smc + SM_SCM);
    float* rmax = (float*)(smc + SM_RMAX);
    float* rsum = (float*)(smc + SM_RSUM);

    const int tid = threadIdx.x;
    const int lane = tid & 31;
    const int warp = tid >> 5;
    const int wm = warp >> 2;   // 0..1
    const int wn = warp & 3;    // 0..3
    const int g = lane >> 2;    // 0..7
    const int t4 = lane & 3;    // 0..3
    const size_t row0 = (size_t)blockIdx.x * 128;

    auto loadB = [&](int gi, int buf) {
        int ch = gi / 40, ks = gi % 40;
        const __half* src = g_w16t + (size_t)(ch * 256 + tid) * HH + ks * 16;
        uint32_t dst = sbase + SM_B + buf * BBUF + tid * BROWB;
        cpasync16(dst, src);
        cpasync16(dst + 16, src + 8);
    };

    // ---- prologue: A tile + first two B stages ----
    {
        const __half* asrc = g_joint + row0 * HH;
        for (int seg = tid; seg < 128 * 80; seg += 256) {
            int r = seg / 80, o = seg % 80;
            uint32_t sa = sbase + SM_A + r * (AROW * 2) + o * 16;
            cpasync16(sa, asrc + (size_t)r * HH + o * 8);
        }
        loadB(0, 0);
        CP_COMMIT();
        loadB(1, 1);
        CP_COMMIT();
    }
    if (tid < 128) {
        rmax[tid] = -INFINITY;
        rsum[tid] = 0.f;
    }

    // tensor accumulators (4 mt x 6 nt)
    float d[4][6][4];
#pragma unroll
    for (int mt = 0; mt < 4; mt++)
#pragma unroll
        for (int nt = 0; nt < 6; nt++)
#pragma unroll
            for (int q = 0; q < 4; q++) d[mt][nt][q] = 0.f;

    // simt accumulators: 2 rows x 16 cols; acc2 holds (even-k, odd-k) f16 sums
    __half2 acc2[2][16];
    float facc[2][16];
    const __half2 hz = __floats2half2_rn(0.f, 0.f);
#pragma unroll
    for (int r = 0; r < 2; r++)
#pragma unroll
        for (int c = 0; c < 16; c++) {
            acc2[r][c] = hz;
            facc[r][c] = 0.f;
        }

    const uint32_t a_lane_row = (uint32_t)(wm * 64 + (lane & 15));
    const uint32_t a_lane_coloff = (uint32_t)((lane >> 4) << 3);
    const uint32_t b_lane_n = (uint32_t)(wn * 48 + (lane & 7) + ((lane >> 4) << 3));
    const uint32_t b_lane_koff = (uint32_t)(((lane >> 3) & 1) << 3);

    const int srow = wm * 64 + lane * 2;   // simt rows: srow, srow+1
    const int scol0 = 192 + wn * 16;       // simt cols within chunk

    for (int gi = 0; gi < NSTEP; gi++) {
        if (gi == NSTEP - 1) { CP_WAIT(0); } else { CP_WAIT(1); }
        __syncthreads();
        if (gi + 2 < NSTEP) {
            loadB(gi + 2, (gi + 2) % 3);
            CP_COMMIT();
        }

        const int ks = gi % 40;
        const int buf = gi % 3;
        const uint32_t abase =
            sbase + SM_A + (a_lane_row * AROW + (uint32_t)(ks * 16) + a_lane_coloff) * 2;
        const uint32_t bbase =
            sbase + SM_B + buf * BBUF + (b_lane_n * BROW + b_lane_koff) * 2;

        uint32_t a[4][4];
#pragma unroll
        for (int mt = 0; mt < 4; mt++) ldsm_x4(a[mt], abase + mt * 16 * (AROW * 2));

        // ---- tensor: 6 nt (cols wn*48 .. wn*48+47) ----
#pragma unroll
        for (int p = 0; p < 3; p++) {
            uint32_t b[4];
            ldsm_x4(b, bbase + p * 16 * (BROW * 2));
#pragma unroll
            for (int mt = 0; mt < 4; mt++) {
                asm volatile(
                    "mma.sync.aligned.m16n8k16.row.col.f32.f16.f16.f32 "
                    "{%0,%1,%2,%3}, {%4,%5,%6,%7}, {%8,%9}, {%0,%1,%2,%3};"
                    : "+f"(d[mt][2 * p][0]), "+f"(d[mt][2 * p][1]),
                      "+f"(d[mt][2 * p][2]), "+f"(d[mt][2 * p][3])
                    : "r"(a[mt][0]), "r"(a[mt][1]), "r"(a[mt][2]), "r"(a[mt][3]),
                      "r"(b[0]), "r"(b[1]));
                asm volatile(
                    "mma.sync.aligned.m16n8k16.row.col.f32.f16.f16.f32 "
                    "{%0,%1,%2,%3}, {%4,%5,%6,%7}, {%8,%9}, {%0,%1,%2,%3};"
                    : "+f"(d[mt][2 * p + 1][0]), "+f"(d[mt][2 * p + 1][1]),
                      "+f"(d[mt][2 * p + 1][2]), "+f"(d[mt][2 * p + 1][3])
                    : "r"(a[mt][0]), "r"(a[mt][1]), "r"(a[mt][2]), "r"(a[mt][3]),
                      "r"(b[2]), "r"(b[3]));
            }
        }

        // ---- SIMT: 2 rows x 16 cols via HFMA2 k-pairs ----
        {
            const char* arow0 = smc + SM_A + ((size_t)srow * AROW + ks * 16) * 2;
            uint4 a0 = *(const uint4*)arow0;
            uint4 a0b = *(const uint4*)(arow0 + 16);
            uint4 a1 = *(const uint4*)(arow0 + AROW * 2);
            uint4 a1b = *(const uint4*)(arow0 + AROW * 2 + 16);
            __half2 ap0[8] = {u2h2(a0.x),  u2h2(a0.y),  u2h2(a0.z),  u2h2(a0.w),
                              u2h2(a0b.x), u2h2(a0b.y), u2h2(a0b.z), u2h2(a0b.w)};
            __half2 ap1[8] = {u2h2(a1.x),  u2h2(a1.y),  u2h2(a1.z),  u2h2(a1.w),
                              u2h2(a1b.x), u2h2(a1b.y), u2h2(a1b.z), u2h2(a1b.w)};
            const char* bb = smc + SM_B + buf * BBUF;
#pragma unroll
            for (int cc = 0; cc < 16; cc++) {
                const char* bcol = bb + (scol0 + cc) * BROWB;
                uint4 b0 = *(const uint4*)bcol;
                uint4 b1 = *(const uint4*)(bcol + 16);
                __half2 bp[8] = {u2h2(b0.x), u2h2(b0.y), u2h2(b0.z), u2h2(b0.w),
                                 u2h2(b1.x), u2h2(b1.y), u2h2(b1.z), u2h2(b1.w)};
                __half2 s0 = acc2[0][cc], s1 = acc2[1][cc];
#pragma unroll
                for (int j = 0; j < 8; j++) {
                    s0 = __hfma2(ap0[j], bp[j], s0);
                    s1 = __hfma2(ap1[j], bp[j], s1);
                }
                acc2[0][cc] = s0;
                acc2[1][cc] = s1;
            }
        }

        // ---- promote f16 partials to f32 every 8 k-steps ----
        if ((gi & 7) == 7) {
#pragma unroll
            for (int r = 0; r < 2; r++)
#pragma unroll
                for (int c = 0; c < 16; c++) {
                    float2 f = __half22float2(acc2[r][c]);
                    facc[r][c] += f.x + f.y;
                    acc2[r][c] = hz;
                }
        }

        if (ks == 39) {
            const int ch = gi / 40;
            // ---- tensor bias ----
#pragma unroll
            for (int nt = 0; nt < 6; nt++) {
                int c = ch * 256 + wn * 48 + nt * 8 + t4 * 2;
                float b0 = __ldg(&bfc[c]), b1 = __ldg(&bfc[c + 1]);
#pragma unroll
                for (int mt = 0; mt < 4; mt++) {
                    d[mt][nt][0] += b0;
                    d[mt][nt][1] += b1;
                    d[mt][nt][2] += b0;
                    d[mt][nt][3] += b1;
                }
            }
            // ---- simt bias ----
            float sv[2][16];
#pragma unroll
            for (int c = 0; c < 16; c++) {
                float bv = __ldg(&bfc[ch * 256 + scol0 + c]);
                sv[0][c] = facc[0][c] + bv;
                sv[1][c] = facc[1][c] + bv;
            }

            // ---- row max: tensor (shuffle over t4) + simt (thread-private) ----
            float lm[4][2];
#pragma unroll
            for (int mt = 0; mt < 4; mt++) {
                float m0 = -INFINITY, m1 = -INFINITY;
#pragma unroll
                for (int nt = 0; nt < 6; nt++) {
                    m0 = fmaxf(m0, fmaxf(d[mt][nt][0], d[mt][nt][1]));
                    m1 = fmaxf(m1, fmaxf(d[mt][nt][2], d[mt][nt][3]));
                }
                lm[mt][0] = m0;
                lm[mt][1] = m1;
            }
#pragma unroll
            for (int mt = 0; mt < 4; mt++)
#pragma unroll
                for (int hh = 0; hh < 2; hh++) {
                    float v = lm[mt][hh];
                    v = fmaxf(v, __shfl_xor_sync(0xffffffffu, v, 1));
                    v = fmaxf(v, __shfl_xor_sync(0xffffffffu, v, 2));
                    lm[mt][hh] = v;
                }
            if (t4 == 0) {
#pragma unroll
                for (int mt = 0; mt < 4; mt++)
#pragma unroll
                    for (int hh = 0; hh < 2; hh++)
                        red[wn * 128 + wm * 64 + mt * 16 + hh * 8 + g] = lm[mt][hh];
            }
            {
                float m0 = -INFINITY, m1 = -INFINITY;
#pragma unroll
                for (int c = 0; c < 16; c++) {
                    m0 = fmaxf(m0, sv[0][c]);
                    m1 = fmaxf(m1, sv[1][c]);
                }
                red2[wn * 128 + srow] = m0;
                red2[wn * 128 + srow + 1] = m1;
            }
            __syncthreads();
            if (tid < 128) {
                float m = fmaxf(fmaxf(red[tid], red[128 + tid]),
                                fmaxf(red[256 + tid], red[384 + tid]));
                m = fmaxf(m, fmaxf(fmaxf(red2[tid], red2[128 + tid]),
                                   fmaxf(red2[256 + tid], red2[384 + tid])));
                scm[tid] = m;
            }
            __syncthreads();

            // ---- sum of exp: tensor + simt ----
            float ls[4][2];
#pragma unroll
            for (int mt = 0; mt < 4; mt++)
#pragma unroll
                for (int hh = 0; hh < 2; hh++) {
                    float cm = scm[wm * 64 + mt * 16 + hh * 8 + g];
                    float s = 0.f;
#pragma unroll
                    for (int nt = 0; nt < 6; nt++)
                        s += ex2sum2((d[mt][nt][2 * hh] - cm) * L2E,
                                     (d[mt][nt][2 * hh + 1] - cm) * L2E);
                    ls[mt][hh] = s;
                }
#pragma unroll
            for (int mt = 0; mt < 4; mt++)
#pragma unroll
                for (int hh = 0; hh < 2; hh++) {
                    float v = ls[mt][hh];
                    v += __shfl_xor_sync(0xffffffffu, v, 1);
                    v += __shfl_xor_sync(0xffffffffu, v, 2);
                    ls[mt][hh] = v;
                }
            if (t4 == 0) {
#pragma unroll
                for (int mt = 0; mt < 4; mt++)
#pragma unroll
                    for (int hh = 0; hh < 2; hh++)
                        red[wn * 128 + wm * 64 + mt * 16 + hh * 8 + g] = ls[mt][hh];
            }
            {
                float cm0 = scm[srow], cm1 = scm[srow + 1];
                float s0 = 0.f, s1 = 0.f;
#pragma unroll
                for (int c = 0; c < 8; c++) {
                    s0 += ex2sum2((sv[0][2 * c] - cm0) * L2E, (sv[0][2 * c + 1] - cm0) * L2E);
                    s1 += ex2sum2((sv[1][2 * c] - cm1) * L2E, (sv[1][2 * c + 1] - cm1) * L2E);
                }
                red2[wn * 128 + srow] = s0;
                red2[wn * 128 + srow + 1] = s1;
            }
            __syncthreads();
            if (tid < 128) {
                float cs = red[tid] + red[128 + tid] + red[256 + tid] + red[384 + tid] +
                           red2[tid] + red2[128 + tid] + red2[256 + tid] + red2[384 + tid];
                float mo = rmax[tid];
                float mn = fmaxf(mo, scm[tid]);
                rsum[tid] = rsum[tid] * exp2f((mo - mn) * L2E) +
                            cs * exp2f((scm[tid] - mn) * L2E);
                rmax[tid] = mn;
            }

            // ---- store f16 logits (tensor + simt) + reset accumulators ----
#pragma unroll
            for (int mt = 0; mt < 4; mt++)
#pragma unroll
                for (int hh = 0; hh < 2; hh++) {
                    size_t r = row0 + wm * 64 + mt * 16 + hh * 8 + g;
#pragma unroll
                    for (int nt = 0; nt < 6; nt++) {
                        int c = ch * 256 + wn * 48 + nt * 8 + t4 * 2;
                        __half2 hv =
                            __floats2half2_rn(d[mt][nt][2 * hh], d[mt][nt][2 * hh + 1]);
                        *(unsigned int*)&g_logits[r * VV + c] = *(unsigned int*)&hv;
                    }
                }
#pragma unroll
            for (int r = 0; r < 2; r++) {
                uint4 o0, o1;
                __half2 hv;
                hv = __floats2half2_rn(sv[r][0], sv[r][1]);   o0.x = *(uint32_t*)&hv;
                hv = __floats2half2_rn(sv[r][2], sv[r][3]);   o0.y = *(uint32_t*)&hv;
                hv = __floats2half2_rn(sv[r][4], sv[r][5]);   o0.z = *(uint32_t*)&hv;
                hv = __floats2half2_rn(sv[r][6], sv[r][7]);   o0.w = *(uint32_t*)&hv;
                hv = __floats2half2_rn(sv[r][8], sv[r][9]);   o1.x = *(uint32_t*)&hv;
                hv = __floats2half2_rn(sv[r][10], sv[r][11]); o1.y = *(uint32_t*)&hv;
                hv = __floats2half2_rn(sv[r][12], sv[r][13]); o1.z = *(uint32_t*)&hv;
                hv = __floats2half2_rn(sv[r][14], sv[r][15]); o1.w = *(uint32_t*)&hv;
                __half* dst = &g_logits[(row0 + srow + r) * VV + ch * 256 + scol0];
                *(uint4*)dst = o0;
                *(uint4*)(dst + 8) = o1;
            }
#pragma unroll
            for (int mt = 0; mt < 4; mt++)
#pragma unroll
                for (int nt = 0; nt < 6; nt++)
#pragma unroll
                    for (int q = 0; q < 4; q++) d[mt][nt][q] = 0.f;
#pragma unroll
            for (int r = 0; r < 2; r++)
#pragma unroll
                for (int c = 0; c < 16; c++) facc[r][c] = 0.f;
        }
    }

    // ---- finalize: rls then normalize ----
    __syncthreads();
    if (tid < 128) scm[tid] = logf(rsum[tid]) + rmax[tid];
    __syncthreads();

    for (int p = tid; p < 128 * 256; p += 256) {
        int r = p >> 8;
        int c4 = p & 255;
        float rls = scm[r];
        uint2 lv = *(const uint2*)&g_logits[(row0 + r) * VV + c4 * 4];
        float2 f0 = __half22float2(*(__half2*)&lv.x);
        float2 f1 = __half22float2(*(__half2*)&lv.y);
        float4 o;
        o.x = f0.x - rls;
        o.y = f0.y - rls;
        o.z = f1.x - rls;
        o.w = f1.y - rls;
        *(float4*)&out[(row0 + r) * VV + c4 * 4] = o;
    }
}

// ===========================================================================
extern "C" void kernel_launch(void* const* d_in, const int* in_sizes, int n_in,
                              void* d_out, int out_size) {
    const float* enc_out = (const float*)d_in[0];
    const float* pred_out = (const float*)d_in[1];
    const float* W_enc = (const float*)d_in[2];
    const float* b_enc = (const float*)d_in[3];
    const float* W_pred = (const float*)d_in[4];
    const float* b_pred = (const float*)d_in[5];
    const float* W_fc = (const float*)d_in[6];
    const float* b_fc = (const float*)d_in[7];
    float* out = (float*)d_out;

    cudaFuncSetAttribute(joint_gemm, cudaFuncAttributeMaxDynamicSharedMemorySize,
                         SM_TOTAL);

    convert_wfc<<<dim3(VV / 32, HH / 32), 256>>>(W_fc);
    proj_gemm<<<dim3((BB * TT) / 64, HH / 64, 5), 256>>>(enc_out, W_enc, 0);
    proj_gemm<<<dim3((BB * UU) / 64, HH / 64, 5), 256>>>(pred_out, W_pred, 1);
    proj_reduce<<<(BB * TT * HH + BB * UU * HH) / 256, 256>>>(b_enc, b_pred);
    tanh_joint<<<MTOT / 32, 256>>>();
    joint_gemm<<<MTOT / 128, 256, SM_TOTAL>>>(b_fc, out);
}

// round 8
// speedup vs baseline: 1.4796x; 1.4796x over previous
#include <cuda_runtime.h>
#include <cuda_fp16.h>
#include <math.h>
#include <stdint.h>

#define BB 4
#define TT 256
#define UU 64
#define DD 640
#define HH 640
#define VV 1024
#define MTOT (BB*TT*UU)   // 65536
#define L2E 1.4426950408889634f

#define AROW 648          // f16 units per A row in SMEM (row stride 1296B)
#define BROW 24           // f16 units per B row in SMEM (16 + 8 pad, 48B)
#define BROWB 48
#define BBUF (256*BROWB)  // 12288 bytes per B stage
#define NSTEP 160         // 4 chunks x 40 k-steps

// ---- static device scratch ----
__device__ float  g_enc[BB*TT*HH];
__device__ float  g_pred[BB*UU*HH];
__device__ float  g_part[5*BB*TT*HH];
__device__ float  g_partp[5*BB*UU*HH];
__device__ __half g_w16t[VV*HH];                 // W_fc^T f16: [n][k]
__device__ __half g_logits[(size_t)MTOT*VV];     // unnormalized logits f16

__device__ __forceinline__ uint32_t smem_u32(const void* p) {
    uint32_t a;
    asm("{ .reg .u64 t; cvta.to.shared.u64 t, %1; cvt.u32.u64 %0, t; }"
        : "=r"(a) : "l"(p));
    return a;
}
__device__ __forceinline__ void cpasync16(uint32_t dst, const void* src) {
    asm volatile("cp.async.ca.shared.global [%0], [%1], 16;" ::"r"(dst), "l"(src));
}
#define CP_COMMIT() asm volatile("cp.async.commit_group;")
#define CP_WAIT(n) asm volatile("cp.async.wait_group %0;" ::"n"(n))

__device__ __forceinline__ void ldsm_x4(uint32_t* r, uint32_t addr) {
    asm volatile("ldmatrix.sync.aligned.m8n8.x4.shared.b16 {%0,%1,%2,%3}, [%4];"
                 : "=r"(r[0]), "=r"(r[1]), "=r"(r[2]), "=r"(r[3]) : "r"(addr));
}
__device__ __forceinline__ float ex2sum2(float x0, float x1) {
    __half2 h = __floats2half2_rn(x0, x1);
    unsigned int u = *(unsigned int*)&h, o;
    asm("ex2.approx.f16x2 %0, %1;" : "=r"(o) : "r"(u));
    float2 f = __half22float2(*(__half2*)&o);
    return f.x + f.y;
}
__device__ __forceinline__ float tanhf_fast(float x) {
    float r;
    asm("tanh.approx.f32 %0, %1;" : "=f"(r) : "f"(x));
    return r;
}

// ===========================================================================
// W_fc fp32 [k][n] -> f16 transposed [n][k]
// ===========================================================================
__global__ __launch_bounds__(256) void convert_wfc(const float* __restrict__ Wfc) {
    __shared__ float t[32][33];
    int n0 = blockIdx.x * 32, k0 = blockIdx.y * 32;
    int tx = threadIdx.x & 31, ty = threadIdx.x >> 5;
#pragma unroll
    for (int j = 0; j < 4; j++)
        t[ty + 8 * j][tx] = Wfc[(size_t)(k0 + ty + 8 * j) * VV + n0 + tx];
    __syncthreads();
#pragma unroll
    for (int j = 0; j < 4; j++)
        g_w16t[(size_t)(n0 + ty + 8 * j) * HH + k0 + tx] = __float2half(t[tx][ty + 8 * j]);
}

// ===========================================================================
// Projection GEMM (split-K by 5) + reduce
// ===========================================================================
__global__ __launch_bounds__(256) void proj_gemm(const float* __restrict__ X,
                                                 const float* __restrict__ W, int which) {
    float* C = which ? g_partp : g_part;
    const int Mrows = which ? (BB * UU) : (BB * TT);
    __shared__ float As[16][65];
    __shared__ float Bs[16][65];
    const int tid = threadIdx.x;
    const int bm = blockIdx.x * 64, bn = blockIdx.y * 64, kz = blockIdx.z;
    const int ty = tid / 16, tx = tid % 16;
    float c[4][4];
#pragma unroll
    for (int i = 0; i < 4; i++)
#pragma unroll
        for (int j = 0; j < 4; j++) c[i][j] = 0.f;
    for (int k0 = kz * 128; k0 < kz * 128 + 128; k0 += 16) {
        for (int l = tid; l < 64 * 16; l += 256) {
            int row = l >> 4, kk = l & 15;
            As[kk][row] = X[(size_t)(bm + row) * DD + k0 + kk];
        }
        for (int l = tid; l < 16 * 64; l += 256) {
            int kk = l >> 6, col = l & 63;
            Bs[kk][col] = W[(size_t)(k0 + kk) * HH + bn + col];
        }
        __syncthreads();
#pragma unroll
        for (int kk = 0; kk < 16; kk++) {
            float a[4], b[4];
#pragma unroll
            for (int i = 0; i < 4; i++) a[i] = As[kk][ty * 4 + i];
#pragma unroll
            for (int j = 0; j < 4; j++) b[j] = Bs[kk][tx * 4 + j];
#pragma unroll
            for (int i = 0; i < 4; i++)
#pragma unroll
                for (int j = 0; j < 4; j++) c[i][j] += a[i] * b[j];
        }
        __syncthreads();
    }
    float* Cz = C + (size_t)kz * Mrows * HH;
#pragma unroll
    for (int i = 0; i < 4; i++)
#pragma unroll
        for (int j = 0; j < 4; j++)
            Cz[(size_t)(bm + ty * 4 + i) * HH + bn + tx * 4 + j] = c[i][j];
}

__global__ __launch_bounds__(256) void proj_reduce(const float* __restrict__ b_enc,
                                                   const float* __restrict__ b_pred) {
    int idx = blockIdx.x * 256 + threadIdx.x;
    const int encN = BB * TT * HH, predN = BB * UU * HH;
    if (idx < encN) {
        float s = b_enc[idx % HH];
#pragma unroll
        for (int z = 0; z < 5; z++) s += g_part[(size_t)z * encN + idx];
        g_enc[idx] = s;
    } else {
        int j = idx - encN;
        if (j < predN) {
            float s = b_pred[j % HH];
#pragma unroll
            for (int z = 0; z < 5; z++) s += g_partp[(size_t)z * predN + j];
            g_pred[j] = s;
        }
    }
}

// ===========================================================================
// Main kernel: M-tile 64, 2 CTAs/SM. Fused tanh prologue (A built in-kernel
// from g_enc/g_pred: one enc row + the b's pred block, both L2-resident).
// mma.sync m16n8k16 f16->f32, ldmatrix frags, 2-stage cp.async B pipeline.
// 8 warps: wm=warp>>2 (rows 32*wm..), wn=warp&3 (cols 64*wn per 256-chunk).
// Fused online log-softmax; f16 logits staged; normalize tail.
// ===========================================================================
#define SM_A 0
#define SM_B (64 * AROW * 2)           // 82944
#define SM_RED (SM_B + 2 * BBUF)       // 107520
#define SM_SCM (SM_RED + 1024)         // 108544
#define SM_RMAX (SM_SCM + 256)         // 108800
#define SM_RSUM (SM_RMAX + 256)        // 109056
#define SM_TOTAL (SM_RSUM + 256)       // 109312

__global__ __launch_bounds__(256, 2) void joint_gemm(const float* __restrict__ bfc,
                                                     float* __restrict__ out) {
    extern __shared__ char smc[];
    const uint32_t sbase = smem_u32(smc);
    float* red = (float*)(smc + SM_RED);    // [4][64]
    float* scm = (float*)(smc + SM_SCM);    // [64]
    float* rmax = (float*)(smc + SM_RMAX);  // [64]
    float* rsum = (float*)(smc + SM_RSUM);  // [64]

    const int tid = threadIdx.x;
    const int lane = tid & 31;
    const int warp = tid >> 5;
    const int wm = warp >> 2;   // 0..1 -> rows 32*wm
    const int wn = warp & 3;    // 0..3 -> cols 64*wn
    const int g = lane >> 2;    // 0..7
    const int t4 = lane & 3;    // 0..3
    const size_t row0 = (size_t)blockIdx.x * 64;

    auto loadB = [&](int gi, int buf) {
        int ch = gi / 40, ks = gi % 40;
        const __half* src = g_w16t + (size_t)(ch * 256 + tid) * HH + ks * 16;
        uint32_t dst = sbase + SM_B + buf * BBUF + tid * BROWB;
        cpasync16(dst, src);
        cpasync16(dst + 16, src + 8);
    };

    // ---- B stages 0,1 first (overlap with tanh A-build) ----
    loadB(0, 0);
    CP_COMMIT();
    loadB(1, 1);
    CP_COMMIT();

    // ---- build A = f16(tanh(enc_row + pred_block)) directly in SMEM ----
    {
        const float* encr = g_enc + (size_t)blockIdx.x * HH;       // 1 enc row
        const float* predb = g_pred + (size_t)(blockIdx.x / 256) * UU * HH;
        for (int e = tid; e < 64 * 160; e += 256) {
            int i = e / 160;
            int h4 = (e - i * 160) * 4;
            float4 p = *(const float4*)&predb[(size_t)i * HH + h4];
            float4 q = *(const float4*)&encr[h4];
            __half2 h0 = __floats2half2_rn(tanhf_fast(p.x + q.x), tanhf_fast(p.y + q.y));
            __half2 h1 = __floats2half2_rn(tanhf_fast(p.z + q.z), tanhf_fast(p.w + q.w));
            uint2 o = {*(uint32_t*)&h0, *(uint32_t*)&h1};
            *(uint2*)(smc + SM_A + i * (AROW * 2) + h4 * 2) = o;
        }
    }
    if (tid < 64) {
        rmax[tid] = -INFINITY;
        rsum[tid] = 0.f;
    }

    float d[2][8][4];
#pragma unroll
    for (int mt = 0; mt < 2; mt++)
#pragma unroll
        for (int nt = 0; nt < 8; nt++)
#pragma unroll
            for (int q = 0; q < 4; q++) d[mt][nt][q] = 0.f;

    const uint32_t a_lane_row = (uint32_t)(wm * 32 + (lane & 15));
    const uint32_t a_lane_coloff = (uint32_t)((lane >> 4) << 3);
    const uint32_t b_lane_n = (uint32_t)(wn * 64 + (lane & 7) + ((lane >> 4) << 3));
    const uint32_t b_lane_koff = (uint32_t)(((lane >> 3) & 1) << 3);

    for (int gi = 0; gi < NSTEP; gi++) {
        if (gi == NSTEP - 1) { CP_WAIT(0); } else { CP_WAIT(1); }
        __syncthreads();  // stage gi visible; also covers A build / buf-reuse

        const int ks = gi % 40;
        const int buf = gi & 1;
        const uint32_t abase =
            sbase + SM_A + (a_lane_row * AROW + (uint32_t)(ks * 16) + a_lane_coloff) * 2;
        const uint32_t bbase =
            sbase + SM_B + buf * BBUF + (b_lane_n * BROW + b_lane_koff) * 2;

        uint32_t a[2][4];
#pragma unroll
        for (int mt = 0; mt < 2; mt++) ldsm_x4(a[mt], abase + mt * 16 * (AROW * 2));

#pragma unroll
        for (int p = 0; p < 4; p++) {
            uint32_t b[4];
            ldsm_x4(b, bbase + p * 16 * (BROW * 2));
#pragma unroll
            for (int mt = 0; mt < 2; mt++) {
                asm volatile(
                    "mma.sync.aligned.m16n8k16.row.col.f32.f16.f16.f32 "
                    "{%0,%1,%2,%3}, {%4,%5,%6,%7}, {%8,%9}, {%0,%1,%2,%3};"
                    : "+f"(d[mt][2 * p][0]), "+f"(d[mt][2 * p][1]),
                      "+f"(d[mt][2 * p][2]), "+f"(d[mt][2 * p][3])
                    : "r"(a[mt][0]), "r"(a[mt][1]), "r"(a[mt][2]), "r"(a[mt][3]),
                      "r"(b[0]), "r"(b[1]));
                asm volatile(
                    "mma.sync.aligned.m16n8k16.row.col.f32.f16.f16.f32 "
                    "{%0,%1,%2,%3}, {%4,%5,%6,%7}, {%8,%9}, {%0,%1,%2,%3};"
                    : "+f"(d[mt][2 * p + 1][0]), "+f"(d[mt][2 * p + 1][1]),
                      "+f"(d[mt][2 * p + 1][2]), "+f"(d[mt][2 * p + 1][3])
                    : "r"(a[mt][0]), "r"(a[mt][1]), "r"(a[mt][2]), "r"(a[mt][3]),
                      "r"(b[2]), "r"(b[3]));
            }
        }

        __syncthreads();  // all warps done reading buf before refill
        if (gi + 2 < NSTEP) {
            loadB(gi + 2, buf);
            CP_COMMIT();
        }

        if (ks == 39) {
            const int ch = gi / 40;
            // ---- bias ----
#pragma unroll
            for (int nt = 0; nt < 8; nt++) {
                int c = ch * 256 + wn * 64 + nt * 8 + t4 * 2;
                float b0 = __ldg(&bfc[c]), b1 = __ldg(&bfc[c + 1]);
#pragma unroll
                for (int mt = 0; mt < 2; mt++) {
                    d[mt][nt][0] += b0;
                    d[mt][nt][1] += b1;
                    d[mt][nt][2] += b0;
                    d[mt][nt][3] += b1;
                }
            }
            // ---- chunk row max ----
            float lm[2][2];
#pragma unroll
            for (int mt = 0; mt < 2; mt++) {
                float m0 = -INFINITY, m1 = -INFINITY;
#pragma unroll
                for (int nt = 0; nt < 8; nt++) {
                    m0 = fmaxf(m0, fmaxf(d[mt][nt][0], d[mt][nt][1]));
                    m1 = fmaxf(m1, fmaxf(d[mt][nt][2], d[mt][nt][3]));
                }
                lm[mt][0] = m0;
                lm[mt][1] = m1;
            }
#pragma unroll
            for (int mt = 0; mt < 2; mt++)
#pragma unroll
                for (int hh = 0; hh < 2; hh++) {
                    float v = lm[mt][hh];
                    v = fmaxf(v, __shfl_xor_sync(0xffffffffu, v, 1));
                    v = fmaxf(v, __shfl_xor_sync(0xffffffffu, v, 2));
                    lm[mt][hh] = v;
                }
            if (t4 == 0) {
#pragma unroll
                for (int mt = 0; mt < 2; mt++)
#pragma unroll
                    for (int hh = 0; hh < 2; hh++)
                        red[wn * 64 + wm * 32 + mt * 16 + hh * 8 + g] = lm[mt][hh];
            }
            __syncthreads();
            if (tid < 64)
                scm[tid] = fmaxf(fmaxf(red[tid], red[64 + tid]),
                                 fmaxf(red[128 + tid], red[192 + tid]));
            __syncthreads();

            // ---- chunk sum of exp ----
            float ls[2][2];
#pragma unroll
            for (int mt = 0; mt < 2; mt++)
#pragma unroll
                for (int hh = 0; hh < 2; hh++) {
                    float cm = scm[wm * 32 + mt * 16 + hh * 8 + g];
                    float s = 0.f;
#pragma unroll
                    for (int nt = 0; nt < 8; nt++)
                        s += ex2sum2((d[mt][nt][2 * hh] - cm) * L2E,
                                     (d[mt][nt][2 * hh + 1] - cm) * L2E);
                    ls[mt][hh] = s;
                }
#pragma unroll
            for (int mt = 0; mt < 2; mt++)
#pragma unroll
                for (int hh = 0; hh < 2; hh++) {
                    float v = ls[mt][hh];
                    v += __shfl_xor_sync(0xffffffffu, v, 1);
                    v += __shfl_xor_sync(0xffffffffu, v, 2);
                    ls[mt][hh] = v;
                }
            if (t4 == 0) {
#pragma unroll
                for (int mt = 0; mt < 2; mt++)
#pragma unroll
                    for (int hh = 0; hh < 2; hh++)
                        red[wn * 64 + wm * 32 + mt * 16 + hh * 8 + g] = ls[mt][hh];
            }
            __syncthreads();
            if (tid < 64) {
                float cs = red[tid] + red[64 + tid] + red[128 + tid] + red[192 + tid];
                float mo = rmax[tid];
                float mn = fmaxf(mo, scm[tid]);
                rsum[tid] = rsum[tid] * exp2f((mo - mn) * L2E) +
                            cs * exp2f((scm[tid] - mn) * L2E);
                rmax[tid] = mn;
            }

            // ---- store f16 logits + reset accumulators ----
#pragma unroll
            for (int mt = 0; mt < 2; mt++)
#pragma unroll
                for (int hh = 0; hh < 2; hh++) {
                    size_t r = row0 + wm * 32 + mt * 16 + hh * 8 + g;
#pragma unroll
                    for (int nt = 0; nt < 8; nt++) {
                        int c = ch * 256 + wn * 64 + nt * 8 + t4 * 2;
                        __half2 hv =
                            __floats2half2_rn(d[mt][nt][2 * hh], d[mt][nt][2 * hh + 1]);
                        *(unsigned int*)&g_logits[r * VV + c] = *(unsigned int*)&hv;
                    }
                }
#pragma unroll
            for (int mt = 0; mt < 2; mt++)
#pragma unroll
                for (int nt = 0; nt < 8; nt++)
#pragma unroll
                    for (int q = 0; q < 4; q++) d[mt][nt][q] = 0.f;
        }
    }

    // ---- finalize: rls then normalize ----
    __syncthreads();
    if (tid < 64) scm[tid] = logf(rsum[tid]) + rmax[tid];
    __syncthreads();

    for (int p = tid; p < 64 * 256; p += 256) {
        int r = p >> 8;
        int c4 = p & 255;
        float rls = scm[r];
        uint2 lv = *(const uint2*)&g_logits[(row0 + r) * VV + c4 * 4];
        float2 f0 = __half22float2(*(__half2*)&lv.x);
        float2 f1 = __half22float2(*(__half2*)&lv.y);
        float4 o;
        o.x = f0.x - rls;
        o.y = f0.y - rls;
        o.z = f1.x - rls;
        o.w = f1.y - rls;
        *(float4*)&out[(row0 + r) * VV + c4 * 4] = o;
    }
}

// ===========================================================================
extern "C" void kernel_launch(void* const* d_in, const int* in_sizes, int n_in,
                              void* d_out, int out_size) {
    const float* enc_out = (const float*)d_in[0];
    const float* pred_out = (const float*)d_in[1];
    const float* W_enc = (const float*)d_in[2];
    const float* b_enc = (const float*)d_in[3];
    const float* W_pred = (const float*)d_in[4];
    const float* b_pred = (const float*)d_in[5];
    const float* W_fc = (const float*)d_in[6];
    const float* b_fc = (const float*)d_in[7];
    float* out = (float*)d_out;

    cudaFuncSetAttribute(joint_gemm, cudaFuncAttributeMaxDynamicSharedMemorySize,
                         SM_TOTAL);

    convert_wfc<<<dim3(VV / 32, HH / 32), 256>>>(W_fc);
    proj_gemm<<<dim3((BB * TT) / 64, HH / 64, 5), 256>>>(enc_out, W_enc, 0);
    proj_gemm<<<dim3((BB * UU) / 64, HH / 64, 5), 256>>>(pred_out, W_pred, 1);
    proj_reduce<<<(BB * TT * HH + BB * UU * HH) / 256, 256>>>(b_enc, b_pred);
    joint_gemm<<<MTOT / 64, 256, SM_TOTAL>>>(b_fc, out);
}

// round 9
// speedup vs baseline: 1.5335x; 1.0365x over previous
#include <cuda_runtime.h>
#include <cuda_fp16.h>
#include <math.h>
#include <stdint.h>

#define BB 4
#define TT 256
#define UU 64
#define DD 640
#define HH 640
#define VV 1024
#define MTOT (BB*TT*UU)   // 65536
#define L2E 1.4426950408889634f

#define AROW 648          // f16 units per A row in SMEM
#define BROW 24           // f16 units per B row in SMEM (16 + 8 pad)
#define BROWB 48
#define BBUF (256*BROWB)  // bytes per B stage = 12288
#define NSTEP 160         // 4 chunks x 40 k-steps

// ---- static device scratch ----
__device__ float  g_enc[BB*TT*HH];
__device__ float  g_pred[BB*UU*HH];
__device__ float  g_part[5*BB*TT*HH];
__device__ float  g_partp[5*BB*UU*HH];
__device__ __half g_w16t[VV*HH];                 // W_fc^T f16: [n][k]
__device__ __half g_logits[(size_t)MTOT*VV];     // unnormalized logits f16

__device__ __forceinline__ uint32_t smem_u32(const void* p) {
    uint32_t a;
    asm("{ .reg .u64 t; cvta.to.shared.u64 t, %1; cvt.u32.u64 %0, t; }"
        : "=r"(a) : "l"(p));
    return a;
}
__device__ __forceinline__ void cpasync16(uint32_t dst, const void* src) {
    asm volatile("cp.async.ca.shared.global [%0], [%1], 16;" ::"r"(dst), "l"(src));
}
#define CP_COMMIT() asm volatile("cp.async.commit_group;")
#define CP_WAIT(n) asm volatile("cp.async.wait_group %0;" ::"n"(n))

__device__ __forceinline__ void ldsm_x4(uint32_t* r, uint32_t addr) {
    asm volatile("ldmatrix.sync.aligned.m8n8.x4.shared.b16 {%0,%1,%2,%3}, [%4];"
                 : "=r"(r[0]), "=r"(r[1]), "=r"(r[2]), "=r"(r[3]) : "r"(addr));
}
__device__ __forceinline__ float ex2sum2(float x0, float x1) {
    __half2 h = __floats2half2_rn(x0, x1);
    unsigned int u = *(unsigned int*)&h, o;
    asm("ex2.approx.f16x2 %0, %1;" : "=r"(o) : "r"(u));
    float2 f = __half22float2(*(__half2*)&o);
    return f.x + f.y;
}
__device__ __forceinline__ uint32_t tanh2(float x0, float x1) {
    __half2 h = __floats2half2_rn(x0, x1);
    unsigned int u = *(unsigned int*)&h, o;
    asm("tanh.approx.f16x2 %0, %1;" : "=r"(o) : "r"(u));
    return o;
}

// ===========================================================================
// W_fc fp32 [k][n] -> f16 transposed [n][k]
// ===========================================================================
__global__ __launch_bounds__(256) void convert_wfc(const float* __restrict__ Wfc) {
    __shared__ float t[32][33];
    int n0 = blockIdx.x * 32, k0 = blockIdx.y * 32;
    int tx = threadIdx.x & 31, ty = threadIdx.x >> 5;
#pragma unroll
    for (int j = 0; j < 4; j++)
        t[ty + 8 * j][tx] = Wfc[(size_t)(k0 + ty + 8 * j) * VV + n0 + tx];
    __syncthreads();
#pragma unroll
    for (int j = 0; j < 4; j++)
        g_w16t[(size_t)(n0 + ty + 8 * j) * HH + k0 + tx] = __float2half(t[tx][ty + 8 * j]);
}

// ===========================================================================
// Projection GEMM (split-K by 5) + reduce
// ===========================================================================
__global__ __launch_bounds__(256) void proj_gemm(const float* __restrict__ X,
                                                 const float* __restrict__ W, int which) {
    float* C = which ? g_partp : g_part;
    const int Mrows = which ? (BB * UU) : (BB * TT);
    __shared__ float As[16][65];
    __shared__ float Bs[16][65];
    const int tid = threadIdx.x;
    const int bm = blockIdx.x * 64, bn = blockIdx.y * 64, kz = blockIdx.z;
    const int ty = tid / 16, tx = tid % 16;
    float c[4][4];
#pragma unroll
    for (int i = 0; i < 4; i++)
#pragma unroll
        for (int j = 0; j < 4; j++) c[i][j] = 0.f;
    for (int k0 = kz * 128; k0 < kz * 128 + 128; k0 += 16) {
        for (int l = tid; l < 64 * 16; l += 256) {
            int row = l >> 4, kk = l & 15;
            As[kk][row] = X[(size_t)(bm + row) * DD + k0 + kk];
        }
        for (int l = tid; l < 16 * 64; l += 256) {
            int kk = l >> 6, col = l & 63;
            Bs[kk][col] = W[(size_t)(k0 + kk) * HH + bn + col];
        }
        __syncthreads();
#pragma unroll
        for (int kk = 0; kk < 16; kk++) {
            float a[4], b[4];
#pragma unroll
            for (int i = 0; i < 4; i++) a[i] = As[kk][ty * 4 + i];
#pragma unroll
            for (int j = 0; j < 4; j++) b[j] = Bs[kk][tx * 4 + j];
#pragma unroll
            for (int i = 0; i < 4; i++)
#pragma unroll
                for (int j = 0; j < 4; j++) c[i][j] += a[i] * b[j];
        }
        __syncthreads();
    }
    float* Cz = C + (size_t)kz * Mrows * HH;
#pragma unroll
    for (int i = 0; i < 4; i++)
#pragma unroll
        for (int j = 0; j < 4; j++)
            Cz[(size_t)(bm + ty * 4 + i) * HH + bn + tx * 4 + j] = c[i][j];
}

__global__ __launch_bounds__(256) void proj_reduce(const float* __restrict__ b_enc,
                                                   const float* __restrict__ b_pred) {
    int idx = blockIdx.x * 256 + threadIdx.x;
    const int encN = BB * TT * HH, predN = BB * UU * HH;
    if (idx < encN) {
        float s = b_enc[idx % HH];
#pragma unroll
        for (int z = 0; z < 5; z++) s += g_part[(size_t)z * encN + idx];
        g_enc[idx] = s;
    } else {
        int j = idx - encN;
        if (j < predN) {
            float s = b_pred[j % HH];
#pragma unroll
            for (int z = 0; z < 5; z++) s += g_partp[(size_t)z * predN + j];
            g_pred[j] = s;
        }
    }
}

// ===========================================================================
// Main kernel (R4 shape, tanh fused into prologue): M-tile 128, 512 CTAs.
// A = f16(tanh(enc_row + pred_row)) built in SMEM from L2-resident g_enc/
// g_pred (2 enc rows + 64 pred rows per CTA). mma.sync m16n8k16 f16->f32,
// ldmatrix frags, 3-stage cp.async B pipeline, one barrier per k-step.
// 8 warps (wm 0..1 x wn 0..3), warp tile 64x64, fused online log-softmax.
// ===========================================================================
#define SM_A 0
#define SM_B (128 * AROW * 2)          // 165888
#define SM_RED (SM_B + 3 * BBUF)       // 202752
#define SM_SCM (SM_RED + 2048)         // 204800
#define SM_RMAX (SM_SCM + 512)         // 205312
#define SM_RSUM (SM_RMAX + 512)        // 205824
#define SM_TOTAL (SM_RSUM + 512)       // 206336

__global__ __launch_bounds__(256, 1) void joint_gemm(const float* __restrict__ bfc,
                                                     float* __restrict__ out) {
    extern __shared__ char smc[];
    const uint32_t sbase = smem_u32(smc);
    float* red = (float*)(smc + SM_RED);
    float* scm = (float*)(smc + SM_SCM);
    float* rmax = (float*)(smc + SM_RMAX);
    float* rsum = (float*)(smc + SM_RSUM);

    const int tid = threadIdx.x;
    const int lane = tid & 31;
    const int warp = tid >> 5;
    const int wm = warp >> 2;   // 0..1
    const int wn = warp & 3;    // 0..3
    const int g = lane >> 2;    // 0..7
    const int t4 = lane & 3;    // 0..3
    const size_t row0 = (size_t)blockIdx.x * 128;

    auto loadB = [&](int gi, int buf) {
        int ch = gi / 40, ks = gi % 40;
        const __half* src = g_w16t + (size_t)(ch * 256 + tid) * HH + ks * 16;
        uint32_t dst = sbase + SM_B + buf * BBUF + tid * BROWB;
        cpasync16(dst, src);
        cpasync16(dst + 16, src + 8);
    };

    // ---- B stages 0,1 first (overlap with tanh A-build) ----
    loadB(0, 0);
    CP_COMMIT();
    loadB(1, 1);
    CP_COMMIT();

    // ---- build A = f16(tanh(enc_row + pred_row)) directly in SMEM ----
    {
        const float* predb = g_pred + (row0 / (TT * UU)) * (size_t)(UU * HH);
        for (int e = tid; e < 128 * 160; e += 256) {
            int i = e / 160;                       // row in tile (0..127)
            int h4 = (e - i * 160) * 4;            // h offset (0..636)
            const float* encr = g_enc + (size_t)((row0 + i) >> 6) * HH;
            const float* predr = predb + (size_t)((row0 + i) & 63) * HH;
            float4 p = *(const float4*)&predr[h4];
            float4 q = *(const float4*)&encr[h4];
            uint2 o;
            o.x = tanh2(p.x + q.x, p.y + q.y);
            o.y = tanh2(p.z + q.z, p.w + q.w);
            *(uint2*)(smc + SM_A + i * (AROW * 2) + h4 * 2) = o;
        }
    }
    if (tid < 128) {
        rmax[tid] = -INFINITY;
        rsum[tid] = 0.f;
    }

    float d[4][8][4];
#pragma unroll
    for (int mt = 0; mt < 4; mt++)
#pragma unroll
        for (int nt = 0; nt < 8; nt++)
#pragma unroll
            for (int q = 0; q < 4; q++) d[mt][nt][q] = 0.f;

    const uint32_t a_lane_row = (uint32_t)(wm * 64 + (lane & 15));
    const uint32_t a_lane_coloff = (uint32_t)((lane >> 4) << 3);
    const uint32_t b_lane_n = (uint32_t)(wn * 64 + (lane & 7) + ((lane >> 4) << 3));
    const uint32_t b_lane_koff = (uint32_t)(((lane >> 3) & 1) << 3);

    for (int gi = 0; gi < NSTEP; gi++) {
        if (gi == NSTEP - 1) { CP_WAIT(0); } else { CP_WAIT(1); }
        __syncthreads();  // stage gi visible; at gi=0 also covers A build
        if (gi + 2 < NSTEP) {
            loadB(gi + 2, (gi + 2) % 3);
            CP_COMMIT();
        }

        const int ks = gi % 40;
        const int buf = gi % 3;
        const uint32_t abase =
            sbase + SM_A + (a_lane_row * AROW + (uint32_t)(ks * 16) + a_lane_coloff) * 2;
        const uint32_t bbase =
            sbase + SM_B + buf * BBUF + (b_lane_n * BROW + b_lane_koff) * 2;

        uint32_t a[4][4];
#pragma unroll
        for (int mt = 0; mt < 4; mt++) ldsm_x4(a[mt], abase + mt * 16 * (AROW * 2));

#pragma unroll
        for (int p = 0; p < 4; p++) {
            uint32_t b[4];
            ldsm_x4(b, bbase + p * 16 * (BROW * 2));
#pragma unroll
            for (int mt = 0; mt < 4; mt++) {
                asm volatile(
                    "mma.sync.aligned.m16n8k16.row.col.f32.f16.f16.f32 "
                    "{%0,%1,%2,%3}, {%4,%5,%6,%7}, {%8,%9}, {%0,%1,%2,%3};"
                    : "+f"(d[mt][2 * p][0]), "+f"(d[mt][2 * p][1]),
                      "+f"(d[mt][2 * p][2]), "+f"(d[mt][2 * p][3])
                    : "r"(a[mt][0]), "r"(a[mt][1]), "r"(a[mt][2]), "r"(a[mt][3]),
                      "r"(b[0]), "r"(b[1]));
                asm volatile(
                    "mma.sync.aligned.m16n8k16.row.col.f32.f16.f16.f32 "
                    "{%0,%1,%2,%3}, {%4,%5,%6,%7}, {%8,%9}, {%0,%1,%2,%3};"
                    : "+f"(d[mt][2 * p + 1][0]), "+f"(d[mt][2 * p + 1][1]),
                      "+f"(d[mt][2 * p + 1][2]), "+f"(d[mt][2 * p + 1][3])
                    : "r"(a[mt][0]), "r"(a[mt][1]), "r"(a[mt][2]), "r"(a[mt][3]),
                      "r"(b[2]), "r"(b[3]));
            }
        }

        if (ks == 39) {
            const int ch = gi / 40;
            // ---- bias ----
#pragma unroll
            for (int nt = 0; nt < 8; nt++) {
                int c = ch * 256 + wn * 64 + nt * 8 + t4 * 2;
                float b0 = __ldg(&bfc[c]), b1 = __ldg(&bfc[c + 1]);
#pragma unroll
                for (int mt = 0; mt < 4; mt++) {
                    d[mt][nt][0] += b0;
                    d[mt][nt][1] += b1;
                    d[mt][nt][2] += b0;
                    d[mt][nt][3] += b1;
                }
            }
            // ---- chunk row max ----
            float lm[4][2];
#pragma unroll
            for (int mt = 0; mt < 4; mt++) {
                float m0 = -INFINITY, m1 = -INFINITY;
#pragma unroll
                for (int nt = 0; nt < 8; nt++) {
                    m0 = fmaxf(m0, fmaxf(d[mt][nt][0], d[mt][nt][1]));
                    m1 = fmaxf(m1, fmaxf(d[mt][nt][2], d[mt][nt][3]));
                }
                lm[mt][0] = m0;
                lm[mt][1] = m1;
            }
#pragma unroll
            for (int mt = 0; mt < 4; mt++)
#pragma unroll
                for (int hh = 0; hh < 2; hh++) {
                    float v = lm[mt][hh];
                    v = fmaxf(v, __shfl_xor_sync(0xffffffffu, v, 1));
                    v = fmaxf(v, __shfl_xor_sync(0xffffffffu, v, 2));
                    lm[mt][hh] = v;
                }
            if (t4 == 0) {
#pragma unroll
                for (int mt = 0; mt < 4; mt++)
#pragma unroll
                    for (int hh = 0; hh < 2; hh++)
                        red[wn * 128 + wm * 64 + mt * 16 + hh * 8 + g] = lm[mt][hh];
            }
            __syncthreads();
            if (tid < 128)
                scm[tid] = fmaxf(fmaxf(red[tid], red[128 + tid]),
                                 fmaxf(red[256 + tid], red[384 + tid]));
            __syncthreads();

            // ---- chunk sum of exp ----
            float ls[4][2];
#pragma unroll
            for (int mt = 0; mt < 4; mt++)
#pragma unroll
                for (int hh = 0; hh < 2; hh++) {
                    float cm = scm[wm * 64 + mt * 16 + hh * 8 + g];
                    float s = 0.f;
#pragma unroll
                    for (int nt = 0; nt < 8; nt++)
                        s += ex2sum2((d[mt][nt][2 * hh] - cm) * L2E,
                                     (d[mt][nt][2 * hh + 1] - cm) * L2E);
                    ls[mt][hh] = s;
                }
#pragma unroll
            for (int mt = 0; mt < 4; mt++)
#pragma unroll
                for (int hh = 0; hh < 2; hh++) {
                    float v = ls[mt][hh];
                    v += __shfl_xor_sync(0xffffffffu, v, 1);
                    v += __shfl_xor_sync(0xffffffffu, v, 2);
                    ls[mt][hh] = v;
                }
            if (t4 == 0) {
#pragma unroll
                for (int mt = 0; mt < 4; mt++)
#pragma unroll
                    for (int hh = 0; hh < 2; hh++)
                        red[wn * 128 + wm * 64 + mt * 16 + hh * 8 + g] = ls[mt][hh];
            }
            __syncthreads();
            if (tid < 128) {
                float cs = red[tid] + red[128 + tid] + red[256 + tid] + red[384 + tid];
                float mo = rmax[tid];
                float mn = fmaxf(mo, scm[tid]);
                rsum[tid] = rsum[tid] * exp2f((mo - mn) * L2E) +
                            cs * exp2f((scm[tid] - mn) * L2E);
                rmax[tid] = mn;
            }

            // ---- store f16 logits + reset accumulators ----
#pragma unroll
            for (int mt = 0; mt < 4; mt++)
#pragma unroll
                for (int hh = 0; hh < 2; hh++) {
                    size_t r = row0 + wm * 64 + mt * 16 + hh * 8 + g;
#pragma unroll
                    for (int nt = 0; nt < 8; nt++) {
                        int c = ch * 256 + wn * 64 + nt * 8 + t4 * 2;
                        __half2 hv =
                            __floats2half2_rn(d[mt][nt][2 * hh], d[mt][nt][2 * hh + 1]);
                        *(unsigned int*)&g_logits[r * VV + c] = *(unsigned int*)&hv;
                    }
                }
#pragma unroll
            for (int mt = 0; mt < 4; mt++)
#pragma unroll
                for (int nt = 0; nt < 8; nt++)
#pragma unroll
                    for (int q = 0; q < 4; q++) d[mt][nt][q] = 0.f;
        }
    }

    // ---- finalize: rls then normalize ----
    __syncthreads();
    if (tid < 128) scm[tid] = logf(rsum[tid]) + rmax[tid];
    __syncthreads();

    for (int p = tid; p < 128 * 256; p += 256) {
        int r = p >> 8;
        int c4 = p & 255;
        float rls = scm[r];
        uint2 lv = *(const uint2*)&g_logits[(row0 + r) * VV + c4 * 4];
        float2 f0 = __half22float2(*(__half2*)&lv.x);
        float2 f1 = __half22float2(*(__half2*)&lv.y);
        float4 o;
        o.x = f0.x - rls;
        o.y = f0.y - rls;
        o.z = f1.x - rls;
        o.w = f1.y - rls;
        *(float4*)&out[(row0 + r) * VV + c4 * 4] = o;
    }
}

// ===========================================================================
extern "C" void kernel_launch(void* const* d_in, const int* in_sizes, int n_in,
                              void* d_out, int out_size) {
    const float* enc_out = (const float*)d_in[0];
    const float* pred_out = (const float*)d_in[1];
    const float* W_enc = (const float*)d_in[2];
    const float* b_enc = (const float*)d_in[3];
    const float* W_pred = (const float*)d_in[4];
    const float* b_pred = (const float*)d_in[5];
    const float* W_fc = (const float*)d_in[6];
    const float* b_fc = (const float*)d_in[7];
    float* out = (float*)d_out;

    cudaFuncSetAttribute(joint_gemm, cudaFuncAttributeMaxDynamicSharedMemorySize,
                         SM_TOTAL);

    convert_wfc<<<dim3(VV / 32, HH / 32), 256>>>(W_fc);
    proj_gemm<<<dim3((BB * TT) / 64, HH / 64, 5), 256>>>(enc_out, W_enc, 0);
    proj_gemm<<<dim3((BB * UU) / 64, HH / 64, 5), 256>>>(pred_out, W_pred, 1);
    proj_reduce<<<(BB * TT * HH + BB * UU * HH) / 256, 256>>>(b_enc, b_pred);
    joint_gemm<<<MTOT / 128, 256, SM_TOTAL>>>(b_fc, out);
}

// round 10
// speedup vs baseline: 1.7610x; 1.1483x over previous
#include <cuda_runtime.h>
#include <cuda_fp16.h>
#include <math.h>
#include <stdint.h>

#define BB 4
#define TT 256
#define UU 64
#define DD 640
#define HH 640
#define VV 1024
#define MTOT (BB*TT*UU)   // 65536
#define L2E 1.4426950408889634f

#define AROW 648          // f16 units per A row in SMEM
#define BROW 24           // f16 units per B row in SMEM (16 + 8 pad)
#define BROWB 48
#define BBUF (256*BROWB)  // bytes per B stage = 12288
#define NSTEP 160         // 4 chunks x 40 k-steps

// ---- static device scratch ----
__device__ float  g_enc[BB*TT*HH];
__device__ float  g_pred[BB*UU*HH];
__device__ float  g_part[5*BB*TT*HH];
__device__ float  g_partp[5*BB*UU*HH];
__device__ __half g_w16t[VV*HH];                 // W_fc^T f16: [n][k]
__device__ __half g_logits[(size_t)MTOT*VV];     // staged logits f16 (chunks 0-2)

__device__ __forceinline__ uint32_t smem_u32(const void* p) {
    uint32_t a;
    asm("{ .reg .u64 t; cvta.to.shared.u64 t, %1; cvt.u32.u64 %0, t; }"
        : "=r"(a) : "l"(p));
    return a;
}
__device__ __forceinline__ void cpasync16cg(uint32_t dst, const void* src) {
    asm volatile("cp.async.cg.shared.global [%0], [%1], 16;" ::"r"(dst), "l"(src));
}
__device__ __forceinline__ void cpasync16(uint32_t dst, const void* src) {
    asm volatile("cp.async.ca.shared.global [%0], [%1], 16;" ::"r"(dst), "l"(src));
}
#define CP_COMMIT() asm volatile("cp.async.commit_group;")
#define CP_WAIT(n) asm volatile("cp.async.wait_group %0;" ::"n"(n))

__device__ __forceinline__ void ldsm_x4(uint32_t* r, uint32_t addr) {
    asm volatile("ldmatrix.sync.aligned.m8n8.x4.shared.b16 {%0,%1,%2,%3}, [%4];"
                 : "=r"(r[0]), "=r"(r[1]), "=r"(r[2]), "=r"(r[3]) : "r"(addr));
}
__device__ __forceinline__ float ex2sum2(float x0, float x1) {
    __half2 h = __floats2half2_rn(x0, x1);
    unsigned int u = *(unsigned int*)&h, o;
    asm("ex2.approx.f16x2 %0, %1;" : "=r"(o) : "r"(u));
    float2 f = __half22float2(*(__half2*)&o);
    return f.x + f.y;
}
__device__ __forceinline__ uint32_t tanh2(float x0, float x1) {
    __half2 h = __floats2half2_rn(x0, x1);
    unsigned int u = *(unsigned int*)&h, o;
    asm("tanh.approx.f16x2 %0, %1;" : "=r"(o) : "r"(u));
    return o;
}

// ===========================================================================
// Projection GEMM (split-K by 5)
// ===========================================================================
__global__ __launch_bounds__(256) void proj_gemm(const float* __restrict__ X,
                                                 const float* __restrict__ W, int which) {
    float* C = which ? g_partp : g_part;
    const int Mrows = which ? (BB * UU) : (BB * TT);
    __shared__ float As[16][65];
    __shared__ float Bs[16][65];
    const int tid = threadIdx.x;
    const int bm = blockIdx.x * 64, bn = blockIdx.y * 64, kz = blockIdx.z;
    const int ty = tid / 16, tx = tid % 16;
    float c[4][4];
#pragma unroll
    for (int i = 0; i < 4; i++)
#pragma unroll
        for (int j = 0; j < 4; j++) c[i][j] = 0.f;
    for (int k0 = kz * 128; k0 < kz * 128 + 128; k0 += 16) {
        for (int l = tid; l < 64 * 16; l += 256) {
            int row = l >> 4, kk = l & 15;
            As[kk][row] = X[(size_t)(bm + row) * DD + k0 + kk];
        }
        for (int l = tid; l < 16 * 64; l += 256) {
            int kk = l >> 6, col = l & 63;
            Bs[kk][col] = W[(size_t)(k0 + kk) * HH + bn + col];
        }
        __syncthreads();
#pragma unroll
        for (int kk = 0; kk < 16; kk++) {
            float a[4], b[4];
#pragma unroll
            for (int i = 0; i < 4; i++) a[i] = As[kk][ty * 4 + i];
#pragma unroll
            for (int j = 0; j < 4; j++) b[j] = Bs[kk][tx * 4 + j];
#pragma unroll
            for (int i = 0; i < 4; i++)
#pragma unroll
                for (int j = 0; j < 4; j++) c[i][j] += a[i] * b[j];
        }
        __syncthreads();
    }
    float* Cz = C + (size_t)kz * Mrows * HH;
#pragma unroll
    for (int i = 0; i < 4; i++)
#pragma unroll
        for (int j = 0; j < 4; j++)
            Cz[(size_t)(bm + ty * 4 + i) * HH + bn + tx * 4 + j] = c[i][j];
}

// ===========================================================================
// Fused: proj reduce (blocks 0..3199) + W_fc fp32->f16 transpose (3200..3839)
// ===========================================================================
__global__ __launch_bounds__(256) void reduce_convert(const float* __restrict__ b_enc,
                                                      const float* __restrict__ b_pred,
                                                      const float* __restrict__ Wfc) {
    __shared__ float t[32][33];
    const int encN = BB * TT * HH, predN = BB * UU * HH;
    if (blockIdx.x < 3200) {
        int idx = blockIdx.x * 256 + threadIdx.x;
        if (idx < encN) {
            float s = b_enc[idx % HH];
#pragma unroll
            for (int z = 0; z < 5; z++) s += g_part[(size_t)z * encN + idx];
            g_enc[idx] = s;
        } else {
            int j = idx - encN;
            if (j < predN) {
                float s = b_pred[j % HH];
#pragma unroll
                for (int z = 0; z < 5; z++) s += g_partp[(size_t)z * predN + j];
                g_pred[j] = s;
            }
        }
    } else {
        int bid = blockIdx.x - 3200;           // 0..639
        int n0 = (bid & 31) * 32, k0 = (bid >> 5) * 32;
        int tx = threadIdx.x & 31, ty = threadIdx.x >> 5;
#pragma unroll
        for (int j = 0; j < 4; j++)
            t[ty + 8 * j][tx] = Wfc[(size_t)(k0 + ty + 8 * j) * VV + n0 + tx];
        __syncthreads();
#pragma unroll
        for (int j = 0; j < 4; j++)
            g_w16t[(size_t)(n0 + ty + 8 * j) * HH + k0 + tx] =
                __float2half(t[tx][ty + 8 * j]);
    }
}

// ===========================================================================
// Main kernel: M-tile 128, fused tanh prologue, mma.sync m16n8k16 f16->f32,
// 3-stage cp.async.cg B pipeline, one barrier per k-step, fused online
// log-softmax. Chunks 0-2 staged f16 (__stcs); chunk 3 written directly from
// registers after rls is known. Bias cached in SMEM.
// ===========================================================================
#define SM_A 0
#define SM_B (128 * AROW * 2)          // 165888
#define SM_RED (SM_B + 3 * BBUF)       // 202752
#define SM_SCM (SM_RED + 2048)         // 204800
#define SM_RMAX (SM_SCM + 512)         // 205312
#define SM_RSUM (SM_RMAX + 512)        // 205824
#define SM_BIAS (SM_RSUM + 512)        // 206336
#define SM_TOTAL (SM_BIAS + 4096)      // 210432

__global__ __launch_bounds__(256, 1) void joint_gemm(const float* __restrict__ bfc,
                                                     float* __restrict__ out) {
    extern __shared__ char smc[];
    const uint32_t sbase = smem_u32(smc);
    float* red = (float*)(smc + SM_RED);
    float* scm = (float*)(smc + SM_SCM);
    float* rmax = (float*)(smc + SM_RMAX);
    float* rsum = (float*)(smc + SM_RSUM);
    float* sbias = (float*)(smc + SM_BIAS);

    const int tid = threadIdx.x;
    const int lane = tid & 31;
    const int warp = tid >> 5;
    const int wm = warp >> 2;   // 0..1
    const int wn = warp & 3;    // 0..3
    const int g = lane >> 2;    // 0..7
    const int t4 = lane & 3;    // 0..3
    const size_t row0 = (size_t)blockIdx.x * 128;

    auto loadB = [&](int gi, int buf) {
        int ch = gi / 40, ks = gi % 40;
        const __half* src = g_w16t + (size_t)(ch * 256 + tid) * HH + ks * 16;
        uint32_t dst = sbase + SM_B + buf * BBUF + tid * BROWB;
        cpasync16cg(dst, src);
        cpasync16cg(dst + 16, src + 8);
    };

    // ---- B stages 0,1 + bias -> smem (overlap with tanh A-build) ----
    loadB(0, 0);
    cpasync16(sbase + SM_BIAS + tid * 16, bfc + tid * 4);
    CP_COMMIT();
    loadB(1, 1);
    CP_COMMIT();

    // ---- build A = f16(tanh(enc_row + pred_row)) directly in SMEM ----
    {
        const float* predb = g_pred + (row0 / (TT * UU)) * (size_t)(UU * HH);
        for (int e = tid; e < 128 * 160; e += 256) {
            int i = e / 160;
            int h4 = (e - i * 160) * 4;
            const float* encr = g_enc + (size_t)((row0 + i) >> 6) * HH;
            const float* predr = predb + (size_t)((row0 + i) & 63) * HH;
            float4 p = *(const float4*)&predr[h4];
            float4 q = *(const float4*)&encr[h4];
            uint2 o;
            o.x = tanh2(p.x + q.x, p.y + q.y);
            o.y = tanh2(p.z + q.z, p.w + q.w);
            *(uint2*)(smc + SM_A + i * (AROW * 2) + h4 * 2) = o;
        }
    }
    if (tid < 128) {
        rmax[tid] = -INFINITY;
        rsum[tid] = 0.f;
    }

    float d[4][8][4];
#pragma unroll
    for (int mt = 0; mt < 4; mt++)
#pragma unroll
        for (int nt = 0; nt < 8; nt++)
#pragma unroll
            for (int q = 0; q < 4; q++) d[mt][nt][q] = 0.f;

    const uint32_t a_lane_row = (uint32_t)(wm * 64 + (lane & 15));
    const uint32_t a_lane_coloff = (uint32_t)((lane >> 4) << 3);
    const uint32_t b_lane_n = (uint32_t)(wn * 64 + (lane & 7) + ((lane >> 4) << 3));
    const uint32_t b_lane_koff = (uint32_t)(((lane >> 3) & 1) << 3);

    for (int gi = 0; gi < NSTEP; gi++) {
        if (gi == NSTEP - 1) { CP_WAIT(0); } else { CP_WAIT(1); }
        __syncthreads();  // stage gi visible; at gi=0 also covers A build + bias
        if (gi + 2 < NSTEP) {
            loadB(gi + 2, (gi + 2) % 3);
            CP_COMMIT();
        }

        const int ks = gi % 40;
        const int buf = gi % 3;
        const uint32_t abase =
            sbase + SM_A + (a_lane_row * AROW + (uint32_t)(ks * 16) + a_lane_coloff) * 2;
        const uint32_t bbase =
            sbase + SM_B + buf * BBUF + (b_lane_n * BROW + b_lane_koff) * 2;

        uint32_t a[4][4];
#pragma unroll
        for (int mt = 0; mt < 4; mt++) ldsm_x4(a[mt], abase + mt * 16 * (AROW * 2));

#pragma unroll
        for (int p = 0; p < 4; p++) {
            uint32_t b[4];
            ldsm_x4(b, bbase + p * 16 * (BROW * 2));
#pragma unroll
            for (int mt = 0; mt < 4; mt++) {
                asm volatile(
                    "mma.sync.aligned.m16n8k16.row.col.f32.f16.f16.f32 "
                    "{%0,%1,%2,%3}, {%4,%5,%6,%7}, {%8,%9}, {%0,%1,%2,%3};"
                    : "+f"(d[mt][2 * p][0]), "+f"(d[mt][2 * p][1]),
                      "+f"(d[mt][2 * p][2]), "+f"(d[mt][2 * p][3])
                    : "r"(a[mt][0]), "r"(a[mt][1]), "r"(a[mt][2]), "r"(a[mt][3]),
                      "r"(b[0]), "r"(b[1]));
                asm volatile(
                    "mma.sync.aligned.m16n8k16.row.col.f32.f16.f16.f32 "
                    "{%0,%1,%2,%3}, {%4,%5,%6,%7}, {%8,%9}, {%0,%1,%2,%3};"
                    : "+f"(d[mt][2 * p + 1][0]), "+f"(d[mt][2 * p + 1][1]),
                      "+f"(d[mt][2 * p + 1][2]), "+f"(d[mt][2 * p + 1][3])
                    : "r"(a[mt][0]), "r"(a[mt][1]), "r"(a[mt][2]), "r"(a[mt][3]),
                      "r"(b[2]), "r"(b[3]));
            }
        }

        if (ks == 39) {
            const int ch = gi / 40;
            // ---- bias (from SMEM) ----
#pragma unroll
            for (int nt = 0; nt < 8; nt++) {
                int c = ch * 256 + wn * 64 + nt * 8 + t4 * 2;
                float b0 = sbias[c], b1 = sbias[c + 1];
#pragma unroll
                for (int mt = 0; mt < 4; mt++) {
                    d[mt][nt][0] += b0;
                    d[mt][nt][1] += b1;
                    d[mt][nt][2] += b0;
                    d[mt][nt][3] += b1;
                }
            }
            // ---- chunk row max ----
            float lm[4][2];
#pragma unroll
            for (int mt = 0; mt < 4; mt++) {
                float m0 = -INFINITY, m1 = -INFINITY;
#pragma unroll
                for (int nt = 0; nt < 8; nt++) {
                    m0 = fmaxf(m0, fmaxf(d[mt][nt][0], d[mt][nt][1]));
                    m1 = fmaxf(m1, fmaxf(d[mt][nt][2], d[mt][nt][3]));
                }
                lm[mt][0] = m0;
                lm[mt][1] = m1;
            }
#pragma unroll
            for (int mt = 0; mt < 4; mt++)
#pragma unroll
                for (int hh = 0; hh < 2; hh++) {
                    float v = lm[mt][hh];
                    v = fmaxf(v, __shfl_xor_sync(0xffffffffu, v, 1));
                    v = fmaxf(v, __shfl_xor_sync(0xffffffffu, v, 2));
                    lm[mt][hh] = v;
                }
            if (t4 == 0) {
#pragma unroll
                for (int mt = 0; mt < 4; mt++)
#pragma unroll
                    for (int hh = 0; hh < 2; hh++)
                        red[wn * 128 + wm * 64 + mt * 16 + hh * 8 + g] = lm[mt][hh];
            }
            __syncthreads();
            if (tid < 128)
                scm[tid] = fmaxf(fmaxf(red[tid], red[128 + tid]),
                                 fmaxf(red[256 + tid], red[384 + tid]));
            __syncthreads();

            // ---- chunk sum of exp ----
            float ls[4][2];
#pragma unroll
            for (int mt = 0; mt < 4; mt++)
#pragma unroll
                for (int hh = 0; hh < 2; hh++) {
                    float cm = scm[wm * 64 + mt * 16 + hh * 8 + g];
                    float s = 0.f;
#pragma unroll
                    for (int nt = 0; nt < 8; nt++)
                        s += ex2sum2((d[mt][nt][2 * hh] - cm) * L2E,
                                     (d[mt][nt][2 * hh + 1] - cm) * L2E);
                    ls[mt][hh] = s;
                }
#pragma unroll
            for (int mt = 0; mt < 4; mt++)
#pragma unroll
                for (int hh = 0; hh < 2; hh++) {
                    float v = ls[mt][hh];
                    v += __shfl_xor_sync(0xffffffffu, v, 1);
                    v += __shfl_xor_sync(0xffffffffu, v, 2);
                    ls[mt][hh] = v;
                }
            if (t4 == 0) {
#pragma unroll
                for (int mt = 0; mt < 4; mt++)
#pragma unroll
                    for (int hh = 0; hh < 2; hh++)
                        red[wn * 128 + wm * 64 + mt * 16 + hh * 8 + g] = ls[mt][hh];
            }
            __syncthreads();
            if (tid < 128) {
                float cs = red[tid] + red[128 + tid] + red[256 + tid] + red[384 + tid];
                float mo = rmax[tid];
                float mn = fmaxf(mo, scm[tid]);
                rsum[tid] = rsum[tid] * exp2f((mo - mn) * L2E) +
                            cs * exp2f((scm[tid] - mn) * L2E);
                rmax[tid] = mn;
            }

            if (ch < 3) {
                // ---- stage f16 logits (streaming stores) + reset accums ----
#pragma unroll
                for (int mt = 0; mt < 4; mt++)
#pragma unroll
                    for (int hh = 0; hh < 2; hh++) {
                        size_t r = row0 + wm * 64 + mt * 16 + hh * 8 + g;
#pragma unroll
                        for (int nt = 0; nt < 8; nt++) {
                            int c = ch * 256 + wn * 64 + nt * 8 + t4 * 2;
                            __half2 hv = __floats2half2_rn(d[mt][nt][2 * hh],
                                                           d[mt][nt][2 * hh + 1]);
                            __stcs((__half2*)&g_logits[r * VV + c], hv);
                        }
                    }
#pragma unroll
                for (int mt = 0; mt < 4; mt++)
#pragma unroll
                    for (int nt = 0; nt < 8; nt++)
#pragma unroll
                        for (int q = 0; q < 4; q++) d[mt][nt][q] = 0.f;
            }
            // ch==3: keep biased logits in registers for direct output below
        }
    }

    // ---- finalize: rls ----
    __syncthreads();
    if (tid < 128) scm[tid] = logf(rsum[tid]) + rmax[tid];
    __syncthreads();

    // ---- chunk 3 output directly from registers ----
#pragma unroll
    for (int mt = 0; mt < 4; mt++)
#pragma unroll
        for (int hh = 0; hh < 2; hh++) {
            int rl = wm * 64 + mt * 16 + hh * 8 + g;
            float rls = scm[rl];
            size_t r = row0 + rl;
#pragma unroll
            for (int nt = 0; nt < 8; nt++) {
                int c = 768 + wn * 64 + nt * 8 + t4 * 2;
                float2 o;
                o.x = d[mt][nt][2 * hh] - rls;
                o.y = d[mt][nt][2 * hh + 1] - rls;
                __stcs((float2*)&out[r * VV + c], o);
            }
        }

    // ---- normalize staged chunks 0-2 (cols 0..767) ----
    for (int p = tid; p < 128 * 192; p += 256) {
        int r = p / 192;
        int c4 = p - r * 192;
        float rls = scm[r];
        uint2 lv = *(const uint2*)__builtin_assume_aligned(
            &g_logits[(row0 + r) * VV + c4 * 4], 8);
        lv = __ldcs((const uint2*)&g_logits[(row0 + r) * VV + c4 * 4]);
        float2 f0 = __half22float2(*(__half2*)&lv.x);
        float2 f1 = __half22float2(*(__half2*)&lv.y);
        float4 o;
        o.x = f0.x - rls;
        o.y = f0.y - rls;
        o.z = f1.x - rls;
        o.w = f1.y - rls;
        __stcs((float4*)&out[(row0 + r) * VV + c4 * 4], o);
    }
}

// ===========================================================================
extern "C" void kernel_launch(void* const* d_in, const int* in_sizes, int n_in,
                              void* d_out, int out_size) {
    const float* enc_out = (const float*)d_in[0];
    const float* pred_out = (const float*)d_in[1];
    const float* W_enc = (const float*)d_in[2];
    const float* b_enc = (const float*)d_in[3];
    const float* W_pred = (const float*)d_in[4];
    const float* b_pred = (const float*)d_in[5];
    const float* W_fc = (const float*)d_in[6];
    const float* b_fc = (const float*)d_in[7];
    float* out = (float*)d_out;

    cudaFuncSetAttribute(joint_gemm, cudaFuncAttributeMaxDynamicSharedMemorySize,
                         SM_TOTAL);

    proj_gemm<<<dim3((BB * TT) / 64, HH / 64, 5), 256>>>(enc_out, W_enc, 0);
    proj_gemm<<<dim3((BB * UU) / 64, HH / 64, 5), 256>>>(pred_out, W_pred, 1);
    reduce_convert<<<3200 + 640, 256>>>(b_enc, b_pred, W_fc);
    joint_gemm<<<MTOT / 128, 256, SM_TOTAL>>>(b_fc, out);
}

// round 11
// speedup vs baseline: 2.0835x; 1.1831x over previous
#include <cuda_runtime.h>
#include <cuda_fp16.h>
#include <math.h>
#include <stdint.h>

#define BB 4
#define TT 256
#define UU 64
#define DD 640
#define HH 640
#define VV 1024
#define MTOT (BB*TT*UU)   // 65536
#define L2E 1.4426950408889634f

#define AROW 648          // f16 units per A row in SMEM
#define BROW 24           // f16 units per B row in SMEM (16 + 8 pad)
#define BROWB 48
#define BBUF (256*BROWB)  // bytes per B stage = 12288
#define NSTEP 160         // 4 chunks x 40 k-steps
#define NTHR 512          // 16 warps: wm 0..3 x wn 0..3, warp tile 32x64

// ---- static device scratch ----
__device__ float  g_enc[BB*TT*HH];
__device__ float  g_pred[BB*UU*HH];
__device__ float  g_part[5*BB*TT*HH];
__device__ float  g_partp[5*BB*UU*HH];
__device__ __half g_w16t[VV*HH];                 // W_fc^T f16: [n][k]
__device__ __half g_logits[(size_t)MTOT*VV];     // staged logits f16 (chunks 0-2)

__device__ __forceinline__ uint32_t smem_u32(const void* p) {
    uint32_t a;
    asm("{ .reg .u64 t; cvta.to.shared.u64 t, %1; cvt.u32.u64 %0, t; }"
        : "=r"(a) : "l"(p));
    return a;
}
__device__ __forceinline__ void cpasync16cg(uint32_t dst, const void* src) {
    asm volatile("cp.async.cg.shared.global [%0], [%1], 16;" ::"r"(dst), "l"(src));
}
__device__ __forceinline__ void cpasync16(uint32_t dst, const void* src) {
    asm volatile("cp.async.ca.shared.global [%0], [%1], 16;" ::"r"(dst), "l"(src));
}
#define CP_COMMIT() asm volatile("cp.async.commit_group;")
#define CP_WAIT(n) asm volatile("cp.async.wait_group %0;" ::"n"(n))

__device__ __forceinline__ void ldsm_x4(uint32_t* r, uint32_t addr) {
    asm volatile("ldmatrix.sync.aligned.m8n8.x4.shared.b16 {%0,%1,%2,%3}, [%4];"
                 : "=r"(r[0]), "=r"(r[1]), "=r"(r[2]), "=r"(r[3]) : "r"(addr));
}
__device__ __forceinline__ float ex2sum2(float x0, float x1) {
    __half2 h = __floats2half2_rn(x0, x1);
    unsigned int u = *(unsigned int*)&h, o;
    asm("ex2.approx.f16x2 %0, %1;" : "=r"(o) : "r"(u));
    float2 f = __half22float2(*(__half2*)&o);
    return f.x + f.y;
}
__device__ __forceinline__ uint32_t tanh2(float x0, float x1) {
    __half2 h = __floats2half2_rn(x0, x1);
    unsigned int u = *(unsigned int*)&h, o;
    asm("tanh.approx.f16x2 %0, %1;" : "=r"(o) : "r"(u));
    return o;
}

// ===========================================================================
// Projection GEMM (split-K by 5)
// ===========================================================================
__global__ __launch_bounds__(256) void proj_gemm(const float* __restrict__ X,
                                                 const float* __restrict__ W, int which) {
    float* C = which ? g_partp : g_part;
    const int Mrows = which ? (BB * UU) : (BB * TT);
    __shared__ float As[16][65];
    __shared__ float Bs[16][65];
    const int tid = threadIdx.x;
    const int bm = blockIdx.x * 64, bn = blockIdx.y * 64, kz = blockIdx.z;
    const int ty = tid / 16, tx = tid % 16;
    float c[4][4];
#pragma unroll
    for (int i = 0; i < 4; i++)
#pragma unroll
        for (int j = 0; j < 4; j++) c[i][j] = 0.f;
    for (int k0 = kz * 128; k0 < kz * 128 + 128; k0 += 16) {
        for (int l = tid; l < 64 * 16; l += 256) {
            int row = l >> 4, kk = l & 15;
            As[kk][row] = X[(size_t)(bm + row) * DD + k0 + kk];
        }
        for (int l = tid; l < 16 * 64; l += 256) {
            int kk = l >> 6, col = l & 63;
            Bs[kk][col] = W[(size_t)(k0 + kk) * HH + bn + col];
        }
        __syncthreads();
#pragma unroll
        for (int kk = 0; kk < 16; kk++) {
            float a[4], b[4];
#pragma unroll
            for (int i = 0; i < 4; i++) a[i] = As[kk][ty * 4 + i];
#pragma unroll
            for (int j = 0; j < 4; j++) b[j] = Bs[kk][tx * 4 + j];
#pragma unroll
            for (int i = 0; i < 4; i++)
#pragma unroll
                for (int j = 0; j < 4; j++) c[i][j] += a[i] * b[j];
        }
        __syncthreads();
    }
    float* Cz = C + (size_t)kz * Mrows * HH;
#pragma unroll
    for (int i = 0; i < 4; i++)
#pragma unroll
        for (int j = 0; j < 4; j++)
            Cz[(size_t)(bm + ty * 4 + i) * HH + bn + tx * 4 + j] = c[i][j];
}

// ===========================================================================
// Fused: proj reduce (blocks 0..3199) + W_fc fp32->f16 transpose (3200..3839)
// ===========================================================================
__global__ __launch_bounds__(256) void reduce_convert(const float* __restrict__ b_enc,
                                                      const float* __restrict__ b_pred,
                                                      const float* __restrict__ Wfc) {
    __shared__ float t[32][33];
    const int encN = BB * TT * HH, predN = BB * UU * HH;
    if (blockIdx.x < 3200) {
        int idx = blockIdx.x * 256 + threadIdx.x;
        if (idx < encN) {
            float s = b_enc[idx % HH];
#pragma unroll
            for (int z = 0; z < 5; z++) s += g_part[(size_t)z * encN + idx];
            g_enc[idx] = s;
        } else {
            int j = idx - encN;
            if (j < predN) {
                float s = b_pred[j % HH];
#pragma unroll
                for (int z = 0; z < 5; z++) s += g_partp[(size_t)z * predN + j];
                g_pred[j] = s;
            }
        }
    } else {
        int bid = blockIdx.x - 3200;           // 0..639
        int n0 = (bid & 31) * 32, k0 = (bid >> 5) * 32;
        int tx = threadIdx.x & 31, ty = threadIdx.x >> 5;
#pragma unroll
        for (int j = 0; j < 4; j++)
            t[ty + 8 * j][tx] = Wfc[(size_t)(k0 + ty + 8 * j) * VV + n0 + tx];
        __syncthreads();
#pragma unroll
        for (int j = 0; j < 4; j++)
            g_w16t[(size_t)(n0 + ty + 8 * j) * HH + k0 + tx] =
                __float2half(t[tx][ty + 8 * j]);
    }
}

// ===========================================================================
// Main kernel: M-tile 128, 512 threads (16 warps, 4/SMSP for latency hiding),
// warp tile 32x64. Fused tanh prologue, mma.sync m16n8k16 f16->f32, 3-stage
// cp.async.cg B pipeline, one barrier per k-step, fused online log-softmax.
// Chunks 0-2 staged f16 (__stcs); chunk 3 direct from registers.
// ===========================================================================
#define SM_A 0
#define SM_B (128 * AROW * 2)          // 165888
#define SM_RED (SM_B + 3 * BBUF)       // 202752
#define SM_SCM (SM_RED + 2048)         // 204800
#define SM_RMAX (SM_SCM + 512)         // 205312
#define SM_RSUM (SM_RMAX + 512)        // 205824
#define SM_BIAS (SM_RSUM + 512)        // 206336
#define SM_TOTAL (SM_BIAS + 4096)      // 210432

__global__ __launch_bounds__(NTHR, 1) void joint_gemm(const float* __restrict__ bfc,
                                                      float* __restrict__ out) {
    extern __shared__ char smc[];
    const uint32_t sbase = smem_u32(smc);
    float* red = (float*)(smc + SM_RED);    // [4][128] indexed by wn
    float* scm = (float*)(smc + SM_SCM);
    float* rmax = (float*)(smc + SM_RMAX);
    float* rsum = (float*)(smc + SM_RSUM);
    float* sbias = (float*)(smc + SM_BIAS);

    const int tid = threadIdx.x;
    const int lane = tid & 31;
    const int warp = tid >> 5;
    const int wm = warp >> 2;   // 0..3 -> rows 32*wm
    const int wn = warp & 3;    // 0..3 -> cols 64*wn
    const int g = lane >> 2;    // 0..7
    const int t4 = lane & 3;    // 0..3
    const size_t row0 = (size_t)blockIdx.x * 128;

    // stage B tile: 512 threads x one 16B cp.async = 8192B
    auto loadB = [&](int gi, int buf) {
        int ch = gi / 40, ks = gi % 40;
        int n = tid >> 1, h = tid & 1;
        const __half* src = g_w16t + (size_t)(ch * 256 + n) * HH + ks * 16 + h * 8;
        uint32_t dst = sbase + SM_B + buf * BBUF + n * BROWB + h * 16;
        cpasync16cg(dst, src);
    };

    // ---- B stages 0,1 + bias -> smem (overlap with tanh A-build) ----
    loadB(0, 0);
    if (tid < 256) cpasync16(sbase + SM_BIAS + tid * 16, bfc + tid * 4);
    CP_COMMIT();
    loadB(1, 1);
    CP_COMMIT();

    // ---- build A = f16(tanh(enc_row + pred_row)) directly in SMEM ----
    {
        const float* predb = g_pred + (row0 / (TT * UU)) * (size_t)(UU * HH);
        for (int e = tid; e < 128 * 160; e += NTHR) {
            int i = e / 160;
            int h4 = (e - i * 160) * 4;
            const float* encr = g_enc + (size_t)((row0 + i) >> 6) * HH;
            const float* predr = predb + (size_t)((row0 + i) & 63) * HH;
            float4 p = *(const float4*)&predr[h4];
            float4 q = *(const float4*)&encr[h4];
            uint2 o;
            o.x = tanh2(p.x + q.x, p.y + q.y);
            o.y = tanh2(p.z + q.z, p.w + q.w);
            *(uint2*)(smc + SM_A + i * (AROW * 2) + h4 * 2) = o;
        }
    }
    if (tid < 128) {
        rmax[tid] = -INFINITY;
        rsum[tid] = 0.f;
    }

    float d[2][8][4];
#pragma unroll
    for (int mt = 0; mt < 2; mt++)
#pragma unroll
        for (int nt = 0; nt < 8; nt++)
#pragma unroll
            for (int q = 0; q < 4; q++) d[mt][nt][q] = 0.f;

    const uint32_t a_lane_row = (uint32_t)(wm * 32 + (lane & 15));
    const uint32_t a_lane_coloff = (uint32_t)((lane >> 4) << 3);
    const uint32_t b_lane_n = (uint32_t)(wn * 64 + (lane & 7) + ((lane >> 4) << 3));
    const uint32_t b_lane_koff = (uint32_t)(((lane >> 3) & 1) << 3);

    for (int gi = 0; gi < NSTEP; gi++) {
        if (gi == NSTEP - 1) { CP_WAIT(0); } else { CP_WAIT(1); }
        __syncthreads();  // stage gi visible; at gi=0 also covers A build + bias
        if (gi + 2 < NSTEP) {
            loadB(gi + 2, (gi + 2) % 3);
            CP_COMMIT();
        }

        const int ks = gi % 40;
        const int buf = gi % 3;
        const uint32_t abase =
            sbase + SM_A + (a_lane_row * AROW + (uint32_t)(ks * 16) + a_lane_coloff) * 2;
        const uint32_t bbase =
            sbase + SM_B + buf * BBUF + (b_lane_n * BROW + b_lane_koff) * 2;

        uint32_t a[2][4];
#pragma unroll
        for (int mt = 0; mt < 2; mt++) ldsm_x4(a[mt], abase + mt * 16 * (AROW * 2));

#pragma unroll
        for (int p = 0; p < 4; p++) {
            uint32_t b[4];
            ldsm_x4(b, bbase + p * 16 * (BROW * 2));
#pragma unroll
            for (int mt = 0; mt < 2; mt++) {
                asm volatile(
                    "mma.sync.aligned.m16n8k16.row.col.f32.f16.f16.f32 "
                    "{%0,%1,%2,%3}, {%4,%5,%6,%7}, {%8,%9}, {%0,%1,%2,%3};"
                    : "+f"(d[mt][2 * p][0]), "+f"(d[mt][2 * p][1]),
                      "+f"(d[mt][2 * p][2]), "+f"(d[mt][2 * p][3])
                    : "r"(a[mt][0]), "r"(a[mt][1]), "r"(a[mt][2]), "r"(a[mt][3]),
                      "r"(b[0]), "r"(b[1]));
                asm volatile(
                    "mma.sync.aligned.m16n8k16.row.col.f32.f16.f16.f32 "
                    "{%0,%1,%2,%3}, {%4,%5,%6,%7}, {%8,%9}, {%0,%1,%2,%3};"
                    : "+f"(d[mt][2 * p + 1][0]), "+f"(d[mt][2 * p + 1][1]),
                      "+f"(d[mt][2 * p + 1][2]), "+f"(d[mt][2 * p + 1][3])
                    : "r"(a[mt][0]), "r"(a[mt][1]), "r"(a[mt][2]), "r"(a[mt][3]),
                      "r"(b[2]), "r"(b[3]));
            }
        }

        if (ks == 39) {
            const int ch = gi / 40;
            // ---- bias (from SMEM) ----
#pragma unroll
            for (int nt = 0; nt < 8; nt++) {
                int c = ch * 256 + wn * 64 + nt * 8 + t4 * 2;
                float b0 = sbias[c], b1 = sbias[c + 1];
#pragma unroll
                for (int mt = 0; mt < 2; mt++) {
                    d[mt][nt][0] += b0;
                    d[mt][nt][1] += b1;
                    d[mt][nt][2] += b0;
                    d[mt][nt][3] += b1;
                }
            }
            // ---- chunk row max ----
            float lm[2][2];
#pragma unroll
            for (int mt = 0; mt < 2; mt++) {
                float m0 = -INFINITY, m1 = -INFINITY;
#pragma unroll
                for (int nt = 0; nt < 8; nt++) {
                    m0 = fmaxf(m0, fmaxf(d[mt][nt][0], d[mt][nt][1]));
                    m1 = fmaxf(m1, fmaxf(d[mt][nt][2], d[mt][nt][3]));
                }
                lm[mt][0] = m0;
                lm[mt][1] = m1;
            }
#pragma unroll
            for (int mt = 0; mt < 2; mt++)
#pragma unroll
                for (int hh = 0; hh < 2; hh++) {
                    float v = lm[mt][hh];
                    v = fmaxf(v, __shfl_xor_sync(0xffffffffu, v, 1));
                    v = fmaxf(v, __shfl_xor_sync(0xffffffffu, v, 2));
                    lm[mt][hh] = v;
                }
            if (t4 == 0) {
#pragma unroll
                for (int mt = 0; mt < 2; mt++)
#pragma unroll
                    for (int hh = 0; hh < 2; hh++)
                        red[wn * 128 + wm * 32 + mt * 16 + hh * 8 + g] = lm[mt][hh];
            }
            __syncthreads();
            if (tid < 128)
                scm[tid] = fmaxf(fmaxf(red[tid], red[128 + tid]),
                                 fmaxf(red[256 + tid], red[384 + tid]));
            __syncthreads();

            // ---- chunk sum of exp ----
            float ls[2][2];
#pragma unroll
            for (int mt = 0; mt < 2; mt++)
#pragma unroll
                for (int hh = 0; hh < 2; hh++) {
                    float cm = scm[wm * 32 + mt * 16 + hh * 8 + g];
                    float s = 0.f;
#pragma unroll
                    for (int nt = 0; nt < 8; nt++)
                        s += ex2sum2((d[mt][nt][2 * hh] - cm) * L2E,
                                     (d[mt][nt][2 * hh + 1] - cm) * L2E);
                    ls[mt][hh] = s;
                }
#pragma unroll
            for (int mt = 0; mt < 2; mt++)
#pragma unroll
                for (int hh = 0; hh < 2; hh++) {
                    float v = ls[mt][hh];
                    v += __shfl_xor_sync(0xffffffffu, v, 1);
                    v += __shfl_xor_sync(0xffffffffu, v, 2);
                    ls[mt][hh] = v;
                }
            if (t4 == 0) {
#pragma unroll
                for (int mt = 0; mt < 2; mt++)
#pragma unroll
                    for (int hh = 0; hh < 2; hh++)
                        red[wn * 128 + wm * 32 + mt * 16 + hh * 8 + g] = ls[mt][hh];
            }
            __syncthreads();
            if (tid < 128) {
                float cs = red[tid] + red[128 + tid] + red[256 + tid] + red[384 + tid];
                float mo = rmax[tid];
                float mn = fmaxf(mo, scm[tid]);
                rsum[tid] = rsum[tid] * exp2f((mo - mn) * L2E) +
                            cs * exp2f((scm[tid] - mn) * L2E);
                rmax[tid] = mn;
            }

            if (ch < 3) {
                // ---- stage f16 logits (streaming stores) + reset accums ----
#pragma unroll
                for (int mt = 0; mt < 2; mt++)
#pragma unroll
                    for (int hh = 0; hh < 2; hh++) {
                        size_t r = row0 + wm * 32 + mt * 16 + hh * 8 + g;
#pragma unroll
                        for (int nt = 0; nt < 8; nt++) {
                            int c = ch * 256 + wn * 64 + nt * 8 + t4 * 2;
                            __half2 hv = __floats2half2_rn(d[mt][nt][2 * hh],
                                                           d[mt][nt][2 * hh + 1]);
                            __stcs((__half2*)&g_logits[r * VV + c], hv);
                        }
                    }
#pragma unroll
                for (int mt = 0; mt < 2; mt++)
#pragma unroll
                    for (int nt = 0; nt < 8; nt++)
#pragma unroll
                        for (int q = 0; q < 4; q++) d[mt][nt][q] = 0.f;
            }
            // ch==3: keep biased logits in registers for direct output below
        }
    }

    // ---- finalize: rls ----
    __syncthreads();
    if (tid < 128) scm[tid] = logf(rsum[tid]) + rmax[tid];
    __syncthreads();

    // ---- chunk 3 output directly from registers ----
#pragma unroll
    for (int mt = 0; mt < 2; mt++)
#pragma unroll
        for (int hh = 0; hh < 2; hh++) {
            int rl = wm * 32 + mt * 16 + hh * 8 + g;
            float rls = scm[rl];
            size_t r = row0 + rl;
#pragma unroll
            for (int nt = 0; nt < 8; nt++) {
                int c = 768 + wn * 64 + nt * 8 + t4 * 2;
                float2 o;
                o.x = d[mt][nt][2 * hh] - rls;
                o.y = d[mt][nt][2 * hh + 1] - rls;
                __stcs((float2*)&out[r * VV + c], o);
            }
        }

    // ---- normalize staged chunks 0-2 (cols 0..767) ----
    for (int p = tid; p < 128 * 192; p += NTHR) {
        int r = p / 192;
        int c4 = p - r * 192;
        float rls = scm[r];
        uint2 lv = __ldcs((const uint2*)&g_logits[(row0 + r) * VV + c4 * 4]);
        float2 f0 = __half22float2(*(__half2*)&lv.x);
        float2 f1 = __half22float2(*(__half2*)&lv.y);
        float4 o;
        o.x = f0.x - rls;
        o.y = f0.y - rls;
        o.z = f1.x - rls;
        o.w = f1.y - rls;
        __stcs((float4*)&out[(row0 + r) * VV + c4 * 4], o);
    }
}

// ===========================================================================
extern "C" void kernel_launch(void* const* d_in, const int* in_sizes, int n_in,
                              void* d_out, int out_size) {
    const float* enc_out = (const float*)d_in[0];
    const float* pred_out = (const float*)d_in[1];
    const float* W_enc = (const float*)d_in[2];
    const float* b_enc = (const float*)d_in[3];
    const float* W_pred = (const float*)d_in[4];
    const float* b_pred = (const float*)d_in[5];
    const float* W_fc = (const float*)d_in[6];
    const float* b_fc = (const float*)d_in[7];
    float* out = (float*)d_out;

    cudaFuncSetAttribute(joint_gemm, cudaFuncAttributeMaxDynamicSharedMemorySize,
                         SM_TOTAL);

    proj_gemm<<<dim3((BB * TT) / 64, HH / 64, 5), 256>>>(enc_out, W_enc, 0);
    proj_gemm<<<dim3((BB * UU) / 64, HH / 64, 5), 256>>>(pred_out, W_pred, 1);
    reduce_convert<<<3200 + 640, 256>>>(b_enc, b_pred, W_fc);
    joint_gemm<<<MTOT / 128, NTHR, SM_TOTAL>>>(b_fc, out);
}

// round 12
// speedup vs baseline: 2.1260x; 1.0204x over previous
#include <cuda_runtime.h>
#include <cuda_fp16.h>
#include <math.h>
#include <stdint.h>

#define BB 4
#define TT 256
#define UU 64
#define DD 640
#define HH 640
#define VV 1024
#define MTOT (BB*TT*UU)   // 65536
#define L2E 1.4426950408889634f

#define AROW 648          // f16 units per A row in SMEM
#define BROW 24           // f16 units per B row in SMEM (16 + 8 pad)
#define BROWB 48
#define BBUF (256*BROWB)  // bytes per B stage = 12288
#define NSTEP 160         // 4 chunks x 40 k-steps
#define NTHR 512          // 16 warps: wm 0..3 x wn 0..3, warp tile 32x64

// ---- static device scratch ----
__device__ float  g_enc[BB*TT*HH];
__device__ float  g_pred[BB*UU*HH];
__device__ float  g_part[5*BB*TT*HH];
__device__ float  g_partp[5*BB*UU*HH];
__device__ __half g_w16t[VV*HH];                 // W_fc^T f16: [n][k]
__device__ __half g_logits[(size_t)MTOT*VV];     // staged logits f16 (chunks 0-2)

__device__ __forceinline__ uint32_t smem_u32(const void* p) {
    uint32_t a;
    asm("{ .reg .u64 t; cvta.to.shared.u64 t, %1; cvt.u32.u64 %0, t; }"
        : "=r"(a) : "l"(p));
    return a;
}
__device__ __forceinline__ void cpasync16cg(uint32_t dst, const void* src) {
    asm volatile("cp.async.cg.shared.global [%0], [%1], 16;" ::"r"(dst), "l"(src));
}
__device__ __forceinline__ void cpasync16(uint32_t dst, const void* src) {
    asm volatile("cp.async.ca.shared.global [%0], [%1], 16;" ::"r"(dst), "l"(src));
}
#define CP_COMMIT() asm volatile("cp.async.commit_group;")
#define CP_WAIT(n) asm volatile("cp.async.wait_group %0;" ::"n"(n))

__device__ __forceinline__ void ldsm_x4(uint32_t* r, uint32_t addr) {
    asm volatile("ldmatrix.sync.aligned.m8n8.x4.shared.b16 {%0,%1,%2,%3}, [%4];"
                 : "=r"(r[0]), "=r"(r[1]), "=r"(r[2]), "=r"(r[3]) : "r"(addr));
}
__device__ __forceinline__ float ex2sum2(float x0, float x1) {
    __half2 h = __floats2half2_rn(x0, x1);
    unsigned int u = *(unsigned int*)&h, o;
    asm("ex2.approx.f16x2 %0, %1;" : "=r"(o) : "r"(u));
    float2 f = __half22float2(*(__half2*)&o);
    return f.x + f.y;
}
__device__ __forceinline__ uint32_t tanh2(float x0, float x1) {
    __half2 h = __floats2half2_rn(x0, x1);
    unsigned int u = *(unsigned int*)&h, o;
    asm("tanh.approx.f16x2 %0, %1;" : "=r"(o) : "r"(u));
    return o;
}

// ===========================================================================
// Projection GEMM (split-K by 5)
// ===========================================================================
__global__ __launch_bounds__(256) void proj_gemm(const float* __restrict__ X,
                                                 const float* __restrict__ W, int which) {
    float* C = which ? g_partp : g_part;
    const int Mrows = which ? (BB * UU) : (BB * TT);
    __shared__ float As[16][65];
    __shared__ float Bs[16][65];
    const int tid = threadIdx.x;
    const int bm = blockIdx.x * 64, bn = blockIdx.y * 64, kz = blockIdx.z;
    const int ty = tid / 16, tx = tid % 16;
    float c[4][4];
#pragma unroll
    for (int i = 0; i < 4; i++)
#pragma unroll
        for (int j = 0; j < 4; j++) c[i][j] = 0.f;
    for (int k0 = kz * 128; k0 < kz * 128 + 128; k0 += 16) {
        for (int l = tid; l < 64 * 16; l += 256) {
            int row = l >> 4, kk = l & 15;
            As[kk][row] = X[(size_t)(bm + row) * DD + k0 + kk];
        }
        for (int l = tid; l < 16 * 64; l += 256) {
            int kk = l >> 6, col = l & 63;
            Bs[kk][col] = W[(size_t)(k0 + kk) * HH + bn + col];
        }
        __syncthreads();
#pragma unroll
        for (int kk = 0; kk < 16; kk++) {
            float a[4], b[4];
#pragma unroll
            for (int i = 0; i < 4; i++) a[i] = As[kk][ty * 4 + i];
#pragma unroll
            for (int j = 0; j < 4; j++) b[j] = Bs[kk][tx * 4 + j];
#pragma unroll
            for (int i = 0; i < 4; i++)
#pragma unroll
                for (int j = 0; j < 4; j++) c[i][j] += a[i] * b[j];
        }
        __syncthreads();
    }
    float* Cz = C + (size_t)kz * Mrows * HH;
#pragma unroll
    for (int i = 0; i < 4; i++)
#pragma unroll
        for (int j = 0; j < 4; j++)
            Cz[(size_t)(bm + ty * 4 + i) * HH + bn + tx * 4 + j] = c[i][j];
}

// ===========================================================================
// Fused: proj reduce (blocks 0..3199) + W_fc fp32->f16 transpose (3200..3839)
// ===========================================================================
__global__ __launch_bounds__(256) void reduce_convert(const float* __restrict__ b_enc,
                                                      const float* __restrict__ b_pred,
                                                      const float* __restrict__ Wfc) {
    __shared__ float t[32][33];
    const int encN = BB * TT * HH, predN = BB * UU * HH;
    if (blockIdx.x < 3200) {
        int idx = blockIdx.x * 256 + threadIdx.x;
        if (idx < encN) {
            float s = b_enc[idx % HH];
#pragma unroll
            for (int z = 0; z < 5; z++) s += g_part[(size_t)z * encN + idx];
            g_enc[idx] = s;
        } else {
            int j = idx - encN;
            if (j < predN) {
                float s = b_pred[j % HH];
#pragma unroll
                for (int z = 0; z < 5; z++) s += g_partp[(size_t)z * predN + j];
                g_pred[j] = s;
            }
        }
    } else {
        int bid = blockIdx.x - 3200;           // 0..639
        int n0 = (bid & 31) * 32, k0 = (bid >> 5) * 32;
        int tx = threadIdx.x & 31, ty = threadIdx.x >> 5;
#pragma unroll
        for (int j = 0; j < 4; j++)
            t[ty + 8 * j][tx] = Wfc[(size_t)(k0 + ty + 8 * j) * VV + n0 + tx];
        __syncthreads();
#pragma unroll
        for (int j = 0; j < 4; j++)
            g_w16t[(size_t)(n0 + ty + 8 * j) * HH + k0 + tx] =
                __float2half(t[tx][ty + 8 * j]);
    }
}

// ===========================================================================
// Main kernel: M-tile 128, 512 threads (16 warps), warp tile 32x64.
// DIV/MOD-free hot loop (nested ch/ks, buf = gi&3, incremental B src ptr),
// 4-stage cp.async.cg pipeline (prefetch distance 3, CP_WAIT(2)), one
// barrier per k-step. Fused tanh prologue + online log-softmax; chunks 0-2
// staged f16, chunk 3 direct from registers.
// ===========================================================================
#define SM_A 0
#define SM_B (128 * AROW * 2)          // 165888
#define SM_RED (SM_B + 4 * BBUF)       // 215040
#define SM_SCM (SM_RED + 2048)         // 217088
#define SM_RMAX (SM_SCM + 512)         // 217600
#define SM_RSUM (SM_RMAX + 512)        // 218112
#define SM_BIAS (SM_RSUM + 512)        // 218624
#define SM_TOTAL (SM_BIAS + 4096)      // 222720

__global__ __launch_bounds__(NTHR, 1) void joint_gemm(const float* __restrict__ bfc,
                                                      float* __restrict__ out) {
    extern __shared__ char smc[];
    const uint32_t sbase = smem_u32(smc);
    float* red = (float*)(smc + SM_RED);    // [4][128] indexed by wn
    float* scm = (float*)(smc + SM_SCM);
    float* rmax = (float*)(smc + SM_RMAX);
    float* rsum = (float*)(smc + SM_RSUM);
    float* sbias = (float*)(smc + SM_BIAS);

    const int tid = threadIdx.x;
    const int lane = tid & 31;
    const int warp = tid >> 5;
    const int wm = warp >> 2;   // 0..3 -> rows 32*wm
    const int wn = warp & 3;    // 0..3 -> cols 64*wn
    const int g = lane >> 2;    // 0..7
    const int t4 = lane & 3;    // 0..3
    const size_t row0 = (size_t)blockIdx.x * 128;

    // ---- per-thread B staging state (incremental, no div/mod) ----
    const int bn_row = tid >> 1;          // 0..255
    const int bh = tid & 1;               // 0..1
    const uint32_t bdst0 = sbase + SM_B + bn_row * BROWB + bh * 16;
    const __half* bsrc = g_w16t + (size_t)bn_row * HH + bh * 8;  // stage 0 src

    // ---- prologue: stages 0,1,2 + bias ----
    cpasync16cg(bdst0 + 0 * BBUF, bsrc);
    if (tid < 256) cpasync16(sbase + SM_BIAS + tid * 16, bfc + tid * 4);
    CP_COMMIT();
    cpasync16cg(bdst0 + 1 * BBUF, bsrc + 16);
    CP_COMMIT();
    cpasync16cg(bdst0 + 2 * BBUF, bsrc + 32);
    CP_COMMIT();
    bsrc += 48;                 // next stage to load = 3
    int lks = 3;                // k-step-in-chunk of next load

    // ---- build A = f16(tanh(enc_row + pred_row)) directly in SMEM ----
    {
        const float* predb = g_pred + (row0 / (TT * UU)) * (size_t)(UU * HH);
        for (int e = tid; e < 128 * 160; e += NTHR) {
            int i = e / 160;
            int h4 = (e - i * 160) * 4;
            const float* encr = g_enc + (size_t)((row0 + i) >> 6) * HH;
            const float* predr = predb + (size_t)((row0 + i) & 63) * HH;
            float4 p = *(const float4*)&predr[h4];
            float4 q = *(const float4*)&encr[h4];
            uint2 o;
            o.x = tanh2(p.x + q.x, p.y + q.y);
            o.y = tanh2(p.z + q.z, p.w + q.w);
            *(uint2*)(smc + SM_A + i * (AROW * 2) + h4 * 2) = o;
        }
    }
    if (tid < 128) {
        rmax[tid] = -INFINITY;
        rsum[tid] = 0.f;
    }

    float d[2][8][4];
#pragma unroll
    for (int mt = 0; mt < 2; mt++)
#pragma unroll
        for (int nt = 0; nt < 8; nt++)
#pragma unroll
            for (int q = 0; q < 4; q++) d[mt][nt][q] = 0.f;

    const uint32_t a_lane_row = (uint32_t)(wm * 32 + (lane & 15));
    const uint32_t a_lane_coloff = (uint32_t)((lane >> 4) << 3);
    const uint32_t b_lane_n = (uint32_t)(wn * 64 + (lane & 7) + ((lane >> 4) << 3));
    const uint32_t b_lane_koff = (uint32_t)(((lane >> 3) & 1) << 3);

    const uint32_t abase0 =
        sbase + SM_A + (a_lane_row * AROW + a_lane_coloff) * 2;
    const uint32_t bfrag0 = sbase + SM_B + (b_lane_n * BROW + b_lane_koff) * 2;

    int gi = 0;
    for (int ch = 0; ch < 4; ch++) {
        uint32_t abase = abase0;   // k=0 of this chunk
        for (int ks = 0; ks < 40; ks++, gi++) {
            if (gi == NSTEP - 1) { CP_WAIT(0); } else { CP_WAIT(2); }
            __syncthreads();  // stage gi visible; buffer (gi+3)&3 free

            // prefetch stage gi+3 (incremental source pointer)
            if (gi + 3 < NSTEP) {
                cpasync16cg(bdst0 + ((gi + 3) & 3) * BBUF, bsrc);
                CP_COMMIT();
                if (++lks == 40) {
                    lks = 0;
                    bsrc += 256 * HH - 39 * 16;   // next chunk, k=0
                } else {
                    bsrc += 16;
                }
            }

            const uint32_t bbase = bfrag0 + ((uint32_t)gi & 3u) * BBUF;

            uint32_t a[2][4];
#pragma unroll
            for (int mt = 0; mt < 2; mt++) ldsm_x4(a[mt], abase + mt * 16 * (AROW * 2));

#pragma unroll
            for (int p = 0; p < 4; p++) {
                uint32_t b[4];
                ldsm_x4(b, bbase + p * 16 * (BROW * 2));
#pragma unroll
                for (int mt = 0; mt < 2; mt++) {
                    asm volatile(
                        "mma.sync.aligned.m16n8k16.row.col.f32.f16.f16.f32 "
                        "{%0,%1,%2,%3}, {%4,%5,%6,%7}, {%8,%9}, {%0,%1,%2,%3};"
                        : "+f"(d[mt][2 * p][0]), "+f"(d[mt][2 * p][1]),
                          "+f"(d[mt][2 * p][2]), "+f"(d[mt][2 * p][3])
                        : "r"(a[mt][0]), "r"(a[mt][1]), "r"(a[mt][2]), "r"(a[mt][3]),
                          "r"(b[0]), "r"(b[1]));
                    asm volatile(
                        "mma.sync.aligned.m16n8k16.row.col.f32.f16.f16.f32 "
                        "{%0,%1,%2,%3}, {%4,%5,%6,%7}, {%8,%9}, {%0,%1,%2,%3};"
                        : "+f"(d[mt][2 * p + 1][0]), "+f"(d[mt][2 * p + 1][1]),
                          "+f"(d[mt][2 * p + 1][2]), "+f"(d[mt][2 * p + 1][3])
                        : "r"(a[mt][0]), "r"(a[mt][1]), "r"(a[mt][2]), "r"(a[mt][3]),
                          "r"(b[2]), "r"(b[3]));
                }
            }
            abase += 32;  // next 16 k (f16 = 2B)
        }

        // ================= per-chunk epilogue =================
        {
            // ---- bias (from SMEM) ----
#pragma unroll
            for (int nt = 0; nt < 8; nt++) {
                int c = ch * 256 + wn * 64 + nt * 8 + t4 * 2;
                float b0 = sbias[c], b1 = sbias[c + 1];
#pragma unroll
                for (int mt = 0; mt < 2; mt++) {
                    d[mt][nt][0] += b0;
                    d[mt][nt][1] += b1;
                    d[mt][nt][2] += b0;
                    d[mt][nt][3] += b1;
                }
            }
            // ---- chunk row max ----
            float lm[2][2];
#pragma unroll
            for (int mt = 0; mt < 2; mt++) {
                float m0 = -INFINITY, m1 = -INFINITY;
#pragma unroll
                for (int nt = 0; nt < 8; nt++) {
                    m0 = fmaxf(m0, fmaxf(d[mt][nt][0], d[mt][nt][1]));
                    m1 = fmaxf(m1, fmaxf(d[mt][nt][2], d[mt][nt][3]));
                }
                lm[mt][0] = m0;
                lm[mt][1] = m1;
            }
#pragma unroll
            for (int mt = 0; mt < 2; mt++)
#pragma unroll
                for (int hh = 0; hh < 2; hh++) {
                    float v = lm[mt][hh];
                    v = fmaxf(v, __shfl_xor_sync(0xffffffffu, v, 1));
                    v = fmaxf(v, __shfl_xor_sync(0xffffffffu, v, 2));
                    lm[mt][hh] = v;
                }
            if (t4 == 0) {
#pragma unroll
                for (int mt = 0; mt < 2; mt++)
#pragma unroll
                    for (int hh = 0; hh < 2; hh++)
                        red[wn * 128 + wm * 32 + mt * 16 + hh * 8 + g] = lm[mt][hh];
            }
            __syncthreads();
            if (tid < 128)
                scm[tid] = fmaxf(fmaxf(red[tid], red[128 + tid]),
                                 fmaxf(red[256 + tid], red[384 + tid]));
            __syncthreads();

            // ---- chunk sum of exp ----
            float ls[2][2];
#pragma unroll
            for (int mt = 0; mt < 2; mt++)
#pragma unroll
                for (int hh = 0; hh < 2; hh++) {
                    float cm = scm[wm * 32 + mt * 16 + hh * 8 + g];
                    float s = 0.f;
#pragma unroll
                    for (int nt = 0; nt < 8; nt++)
                        s += ex2sum2((d[mt][nt][2 * hh] - cm) * L2E,
                                     (d[mt][nt][2 * hh + 1] - cm) * L2E);
                    ls[mt][hh] = s;
                }
#pragma unroll
            for (int mt = 0; mt < 2; mt++)
#pragma unroll
                for (int hh = 0; hh < 2; hh++) {
                    float v = ls[mt][hh];
                    v += __shfl_xor_sync(0xffffffffu, v, 1);
                    v += __shfl_xor_sync(0xffffffffu, v, 2);
                    ls[mt][hh] = v;
                }
            if (t4 == 0) {
#pragma unroll
                for (int mt = 0; mt < 2; mt++)
#pragma unroll
                    for (int hh = 0; hh < 2; hh++)
                        red[wn * 128 + wm * 32 + mt * 16 + hh * 8 + g] = ls[mt][hh];
            }
            __syncthreads();
            if (tid < 128) {
                float cs = red[tid] + red[128 + tid] + red[256 + tid] + red[384 + tid];
                float mo = rmax[tid];
                float mn = fmaxf(mo, scm[tid]);
                rsum[tid] = rsum[tid] * exp2f((mo - mn) * L2E) +
                            cs * exp2f((scm[tid] - mn) * L2E);
                rmax[tid] = mn;
            }

            if (ch < 3) {
                // ---- stage f16 logits (streaming stores) + reset accums ----
#pragma unroll
                for (int mt = 0; mt < 2; mt++)
#pragma unroll
                    for (int hh = 0; hh < 2; hh++) {
                        size_t r = row0 + wm * 32 + mt * 16 + hh * 8 + g;
#pragma unroll
                        for (int nt = 0; nt < 8; nt++) {
                            int c = ch * 256 + wn * 64 + nt * 8 + t4 * 2;
                            __half2 hv = __floats2half2_rn(d[mt][nt][2 * hh],
                                                           d[mt][nt][2 * hh + 1]);
                            __stcs((__half2*)&g_logits[r * VV + c], hv);
                        }
                    }
#pragma unroll
                for (int mt = 0; mt < 2; mt++)
#pragma unroll
                    for (int nt = 0; nt < 8; nt++)
#pragma unroll
                        for (int q = 0; q < 4; q++) d[mt][nt][q] = 0.f;
            }
            // ch==3: keep biased logits in registers for direct output below
        }
    }

    // ---- finalize: rls ----
    __syncthreads();
    if (tid < 128) scm[tid] = logf(rsum[tid]) + rmax[tid];
    __syncthreads();

    // ---- chunk 3 output directly from registers ----
#pragma unroll
    for (int mt = 0; mt < 2; mt++)
#pragma unroll
        for (int hh = 0; hh < 2; hh++) {
            int rl = wm * 32 + mt * 16 + hh * 8 + g;
            float rls = scm[rl];
            size_t r = row0 + rl;
#pragma unroll
            for (int nt = 0; nt < 8; nt++) {
                int c = 768 + wn * 64 + nt * 8 + t4 * 2;
                float2 o;
                o.x = d[mt][nt][2 * hh] - rls;
                o.y = d[mt][nt][2 * hh + 1] - rls;
                __stcs((float2*)&out[r * VV + c], o);
            }
        }

    // ---- normalize staged chunks 0-2 (cols 0..767) ----
    for (int p = tid; p < 128 * 192; p += NTHR) {
        int r = p / 192;
        int c4 = p - r * 192;
        float rls = scm[r];
        uint2 lv = __ldcs((const uint2*)&g_logits[(row0 + r) * VV + c4 * 4]);
        float2 f0 = __half22float2(*(__half2*)&lv.x);
        float2 f1 = __half22float2(*(__half2*)&lv.y);
        float4 o;
        o.x = f0.x - rls;
        o.y = f0.y - rls;
        o.z = f1.x - rls;
        o.w = f1.y - rls;
        __stcs((float4*)&out[(row0 + r) * VV + c4 * 4], o);
    }
}

// ===========================================================================
extern "C" void kernel_launch(void* const* d_in, const int* in_sizes, int n_in,
                              void* d_out, int out_size) {
    const float* enc_out = (const float*)d_in[0];
    const float* pred_out = (const float*)d_in[1];
    const float* W_enc = (const float*)d_in[2];
    const float* b_enc = (const float*)d_in[3];
    const float* W_pred = (const float*)d_in[4];
    const float* b_pred = (const float*)d_in[5];
    const float* W_fc = (const float*)d_in[6];
    const float* b_fc = (const float*)d_in[7];
    float* out = (float*)d_out;

    cudaFuncSetAttribute(joint_gemm, cudaFuncAttributeMaxDynamicSharedMemorySize,
                         SM_TOTAL);

    proj_gemm<<<dim3((BB * TT) / 64, HH / 64, 5), 256>>>(enc_out, W_enc, 0);
    proj_gemm<<<dim3((BB * UU) / 64, HH / 64, 5), 256>>>(pred_out, W_pred, 1);
    reduce_convert<<<3200 + 640, 256>>>(b_enc, b_pred, W_fc);
    joint_gemm<<<MTOT / 128, NTHR, SM_TOTAL>>>(b_fc, out);
}

// round 13
// speedup vs baseline: 2.2395x; 1.0534x over previous
#include <cuda_runtime.h>
#include <cuda_fp16.h>
#include <math.h>
#include <stdint.h>

#define BB 4
#define TT 256
#define UU 64
#define DD 640
#define HH 640
#define VV 1024
#define MTOT (BB*TT*UU)   // 65536
#define L2E 1.4426950408889634f

#define AROW 648          // f16 units per A row in SMEM
#define BROW 40           // f16 units per B row in SMEM (32 + 8 pad)
#define BROWB 80
#define BBUF (256*BROWB)  // bytes per B stage = 20480 (BK=32)
#define NSTAGE 80         // 4 chunks x 20 stages (32 k each)
#define NTHR 512          // 16 warps: wm 0..3 x wn 0..3, warp tile 32x64

// ---- static device scratch ----
__device__ float  g_enc[BB*TT*HH];
__device__ float  g_pred[BB*UU*HH];
__device__ float  g_part[5*BB*TT*HH];
__device__ float  g_partp[5*BB*UU*HH];
__device__ __half g_w16t[VV*HH];                 // W_fc^T f16: [n][k]
__device__ __half g_logits[(size_t)MTOT*VV];     // staged logits f16 (chunks 0-2)

__device__ __forceinline__ uint32_t smem_u32(const void* p) {
    uint32_t a;
    asm("{ .reg .u64 t; cvta.to.shared.u64 t, %1; cvt.u32.u64 %0, t; }"
        : "=r"(a) : "l"(p));
    return a;
}
__device__ __forceinline__ void cpasync16cg(uint32_t dst, const void* src) {
    asm volatile("cp.async.cg.shared.global [%0], [%1], 16;" ::"r"(dst), "l"(src));
}
#define CP_COMMIT() asm volatile("cp.async.commit_group;")
#define CP_WAIT(n) asm volatile("cp.async.wait_group %0;" ::"n"(n))

__device__ __forceinline__ void ldsm_x4(uint32_t* r, uint32_t addr) {
    asm volatile("ldmatrix.sync.aligned.m8n8.x4.shared.b16 {%0,%1,%2,%3}, [%4];"
                 : "=r"(r[0]), "=r"(r[1]), "=r"(r[2]), "=r"(r[3]) : "r"(addr));
}
__device__ __forceinline__ float ex2sum2(float x0, float x1) {
    __half2 h = __floats2half2_rn(x0, x1);
    unsigned int u = *(unsigned int*)&h, o;
    asm("ex2.approx.f16x2 %0, %1;" : "=r"(o) : "r"(u));
    float2 f = __half22float2(*(__half2*)&o);
    return f.x + f.y;
}
__device__ __forceinline__ uint32_t tanh2(float x0, float x1) {
    __half2 h = __floats2half2_rn(x0, x1);
    unsigned int u = *(unsigned int*)&h, o;
    asm("tanh.approx.f16x2 %0, %1;" : "=r"(o) : "r"(u));
    return o;
}

// ===========================================================================
// Projection GEMM (split-K by 5)
// ===========================================================================
__global__ __launch_bounds__(256) void proj_gemm(const float* __restrict__ X,
                                                 const float* __restrict__ W, int which) {
    float* C = which ? g_partp : g_part;
    const int Mrows = which ? (BB * UU) : (BB * TT);
    __shared__ float As[16][65];
    __shared__ float Bs[16][65];
    const int tid = threadIdx.x;
    const int bm = blockIdx.x * 64, bn = blockIdx.y * 64, kz = blockIdx.z;
    const int ty = tid / 16, tx = tid % 16;
    float c[4][4];
#pragma unroll
    for (int i = 0; i < 4; i++)
#pragma unroll
        for (int j = 0; j < 4; j++) c[i][j] = 0.f;
    for (int k0 = kz * 128; k0 < kz * 128 + 128; k0 += 16) {
        for (int l = tid; l < 64 * 16; l += 256) {
            int row = l >> 4, kk = l & 15;
            As[kk][row] = X[(size_t)(bm + row) * DD + k0 + kk];
        }
        for (int l = tid; l < 16 * 64; l += 256) {
            int kk = l >> 6, col = l & 63;
            Bs[kk][col] = W[(size_t)(k0 + kk) * HH + bn + col];
        }
        __syncthreads();
#pragma unroll
        for (int kk = 0; kk < 16; kk++) {
            float a[4], b[4];
#pragma unroll
            for (int i = 0; i < 4; i++) a[i] = As[kk][ty * 4 + i];
#pragma unroll
            for (int j = 0; j < 4; j++) b[j] = Bs[kk][tx * 4 + j];
#pragma unroll
            for (int i = 0; i < 4; i++)
#pragma unroll
                for (int j = 0; j < 4; j++) c[i][j] += a[i] * b[j];
        }
        __syncthreads();
    }
    float* Cz = C + (size_t)kz * Mrows * HH;
#pragma unroll
    for (int i = 0; i < 4; i++)
#pragma unroll
        for (int j = 0; j < 4; j++)
            Cz[(size_t)(bm + ty * 4 + i) * HH + bn + tx * 4 + j] = c[i][j];
}

// ===========================================================================
// Fused: proj reduce (blocks 0..3199) + W_fc fp32->f16 transpose (3200..3839)
// ===========================================================================
__global__ __launch_bounds__(256) void reduce_convert(const float* __restrict__ b_enc,
                                                      const float* __restrict__ b_pred,
                                                      const float* __restrict__ Wfc) {
    __shared__ float t[32][33];
    const int encN = BB * TT * HH, predN = BB * UU * HH;
    if (blockIdx.x < 3200) {
        int idx = blockIdx.x * 256 + threadIdx.x;
        if (idx < encN) {
            float s = b_enc[idx % HH];
#pragma unroll
            for (int z = 0; z < 5; z++) s += g_part[(size_t)z * encN + idx];
            g_enc[idx] = s;
        } else {
            int j = idx - encN;
            if (j < predN) {
                float s = b_pred[j % HH];
#pragma unroll
                for (int z = 0; z < 5; z++) s += g_partp[(size_t)z * predN + j];
                g_pred[j] = s;
            }
        }
    } else {
        int bid = blockIdx.x - 3200;           // 0..639
        int n0 = (bid & 31) * 32, k0 = (bid >> 5) * 32;
        int tx = threadIdx.x & 31, ty = threadIdx.x >> 5;
#pragma unroll
        for (int j = 0; j < 4; j++)
            t[ty + 8 * j][tx] = Wfc[(size_t)(k0 + ty + 8 * j) * VV + n0 + tx];
        __syncthreads();
#pragma unroll
        for (int j = 0; j < 4; j++)
            g_w16t[(size_t)(n0 + ty + 8 * j) * HH + k0 + tx] =
                __float2half(t[tx][ty + 8 * j]);
    }
}

// ===========================================================================
// Main kernel: M-tile 128, 512 threads (16 warps), warp tile 32x64.
// BK=32 stages (3 buffers, 20.5KB each): ONE barrier + ONE wait per 32 k
// (80 total, was 160). Two 16-k sub-steps per stage. Fused tanh prologue,
// online log-softmax, chunks 0-2 staged f16, chunk 3 direct from registers.
// ===========================================================================
#define SM_A 0
#define SM_B (128 * AROW * 2)          // 165888
#define SM_RED (SM_B + 3 * BBUF)       // 227328
#define SM_SCM (SM_RED + 2048)         // 229376
#define SM_RMAX (SM_SCM + 512)         // 229888
#define SM_RSUM (SM_RMAX + 512)        // 230400
#define SM_TOTAL (SM_RSUM + 512)       // 230912

__global__ __launch_bounds__(NTHR, 1) void joint_gemm(const float* __restrict__ bfc,
                                                      float* __restrict__ out) {
    extern __shared__ char smc[];
    const uint32_t sbase = smem_u32(smc);
    float* red = (float*)(smc + SM_RED);    // [4][128] indexed by wn
    float* scm = (float*)(smc + SM_SCM);
    float* rmax = (float*)(smc + SM_RMAX);
    float* rsum = (float*)(smc + SM_RSUM);

    const int tid = threadIdx.x;
    const int lane = tid & 31;
    const int warp = tid >> 5;
    const int wm = warp >> 2;   // 0..3 -> rows 32*wm
    const int wn = warp & 3;    // 0..3 -> cols 64*wn
    const int g = lane >> 2;    // 0..7
    const int t4 = lane & 3;    // 0..3
    const size_t row0 = (size_t)blockIdx.x * 128;

    // ---- per-thread B staging state (incremental, no div/mod) ----
    // Each stage: 256 rows x 64B (32 k f16). Thread loads 32B: row tid>>1,
    // half tid&1.
    const int bn_row = tid >> 1;          // 0..255
    const int bh = tid & 1;               // 0..1
    const uint32_t bdst0 = sbase + SM_B + bn_row * BROWB + bh * 32;
    const __half* bsrc = g_w16t + (size_t)bn_row * HH + bh * 16;  // stage 0 src

    // ---- prologue: stages 0,1 ----
    cpasync16cg(bdst0 + 0 * BBUF, bsrc);
    cpasync16cg(bdst0 + 0 * BBUF + 16, bsrc + 8);
    CP_COMMIT();
    cpasync16cg(bdst0 + 1 * BBUF, bsrc + 32);
    cpasync16cg(bdst0 + 1 * BBUF + 16, bsrc + 40);
    CP_COMMIT();
    bsrc += 64;                 // next stage to load = 2
    int lks = 2;                // stage-in-chunk of next load
    int pbuf = 2;               // buffer of next prefetch

    // ---- build A = f16(tanh(enc_row + pred_row)) directly in SMEM ----
    {
        const float* predb = g_pred + (row0 / (TT * UU)) * (size_t)(UU * HH);
        for (int e = tid; e < 128 * 160; e += NTHR) {
            int i = e / 160;
            int h4 = (e - i * 160) * 4;
            const float* encr = g_enc + (size_t)((row0 + i) >> 6) * HH;
            const float* predr = predb + (size_t)((row0 + i) & 63) * HH;
            float4 p = *(const float4*)&predr[h4];
            float4 q = *(const float4*)&encr[h4];
            uint2 o;
            o.x = tanh2(p.x + q.x, p.y + q.y);
            o.y = tanh2(p.z + q.z, p.w + q.w);
            *(uint2*)(smc + SM_A + i * (AROW * 2) + h4 * 2) = o;
        }
    }
    if (tid < 128) {
        rmax[tid] = -INFINITY;
        rsum[tid] = 0.f;
    }

    float d[2][8][4];
#pragma unroll
    for (int mt = 0; mt < 2; mt++)
#pragma unroll
        for (int nt = 0; nt < 8; nt++)
#pragma unroll
            for (int q = 0; q < 4; q++) d[mt][nt][q] = 0.f;

    const uint32_t a_lane_row = (uint32_t)(wm * 32 + (lane & 15));
    const uint32_t a_lane_coloff = (uint32_t)((lane >> 4) << 3);
    const uint32_t b_lane_n = (uint32_t)(wn * 64 + (lane & 7) + ((lane >> 4) << 3));
    const uint32_t b_lane_koff = (uint32_t)(((lane >> 3) & 1) << 3);

    const uint32_t abase0 =
        sbase + SM_A + (a_lane_row * AROW + a_lane_coloff) * 2;
    const uint32_t bfrag0 = sbase + SM_B + (b_lane_n * BROW + b_lane_koff) * 2;

    int gs = 0;        // global stage index 0..79
    int cbuf = 0;      // buffer being consumed
    for (int ch = 0; ch < 4; ch++) {
        uint32_t abase = abase0;   // k=0 of this chunk
        for (int it = 0; it < 20; it++, gs++) {
            __syncthreads();  // all warps done reading buffer pbuf (prev use)

            if (gs + 2 < NSTAGE) {
                cpasync16cg(bdst0 + pbuf * BBUF, bsrc);
                cpasync16cg(bdst0 + pbuf * BBUF + 16, bsrc + 8);
                CP_COMMIT();
                CP_WAIT(2);   // retire group of stage gs
                if (++lks == 20) {
                    lks = 0;
                    bsrc += 256 * HH - 19 * 32;   // next chunk, k=0
                } else {
                    bsrc += 32;
                }
                if (++pbuf == 3) pbuf = 0;
            } else {
                CP_WAIT(0);
            }
            __syncthreads();  // stage gs visible to all warps

            const uint32_t bstage = bfrag0 + (uint32_t)cbuf * BBUF;
            if (++cbuf == 3) cbuf = 0;

            // ---- two 16-k sub-steps ----
#pragma unroll
            for (int s = 0; s < 2; s++) {
                uint32_t a[2][4];
#pragma unroll
                for (int mt = 0; mt < 2; mt++)
                    ldsm_x4(a[mt], abase + s * 32 + mt * 16 * (AROW * 2));
                const uint32_t bb = bstage + s * 32;
#pragma unroll
                for (int p = 0; p < 4; p++) {
                    uint32_t b[4];
                    ldsm_x4(b, bb + p * 16 * (BROW * 2));
#pragma unroll
                    for (int mt = 0; mt < 2; mt++) {
                        asm volatile(
                            "mma.sync.aligned.m16n8k16.row.col.f32.f16.f16.f32 "
                            "{%0,%1,%2,%3}, {%4,%5,%6,%7}, {%8,%9}, {%0,%1,%2,%3};"
                            : "+f"(d[mt][2 * p][0]), "+f"(d[mt][2 * p][1]),
                              "+f"(d[mt][2 * p][2]), "+f"(d[mt][2 * p][3])
                            : "r"(a[mt][0]), "r"(a[mt][1]), "r"(a[mt][2]),
                              "r"(a[mt][3]), "r"(b[0]), "r"(b[1]));
                        asm volatile(
                            "mma.sync.aligned.m16n8k16.row.col.f32.f16.f16.f32 "
                            "{%0,%1,%2,%3}, {%4,%5,%6,%7}, {%8,%9}, {%0,%1,%2,%3};"
                            : "+f"(d[mt][2 * p + 1][0]), "+f"(d[mt][2 * p + 1][1]),
                              "+f"(d[mt][2 * p + 1][2]), "+f"(d[mt][2 * p + 1][3])
                            : "r"(a[mt][0]), "r"(a[mt][1]), "r"(a[mt][2]),
                              "r"(a[mt][3]), "r"(b[2]), "r"(b[3]));
                    }
                }
            }
            abase += 64;  // 32 k consumed (f16 = 2B)
        }

        // ================= per-chunk epilogue =================
        {
            // ---- bias (L2-hot gmem) ----
#pragma unroll
            for (int nt = 0; nt < 8; nt++) {
                int c = ch * 256 + wn * 64 + nt * 8 + t4 * 2;
                float b0 = __ldg(&bfc[c]), b1 = __ldg(&bfc[c + 1]);
#pragma unroll
                for (int mt = 0; mt < 2; mt++) {
                    d[mt][nt][0] += b0;
                    d[mt][nt][1] += b1;
                    d[mt][nt][2] += b0;
                    d[mt][nt][3] += b1;
                }
            }
            // ---- chunk row max ----
            float lm[2][2];
#pragma unroll
            for (int mt = 0; mt < 2; mt++) {
                float m0 = -INFINITY, m1 = -INFINITY;
#pragma unroll
                for (int nt = 0; nt < 8; nt++) {
                    m0 = fmaxf(m0, fmaxf(d[mt][nt][0], d[mt][nt][1]));
                    m1 = fmaxf(m1, fmaxf(d[mt][nt][2], d[mt][nt][3]));
                }
                lm[mt][0] = m0;
                lm[mt][1] = m1;
            }
#pragma unroll
            for (int mt = 0; mt < 2; mt++)
#pragma unroll
                for (int hh = 0; hh < 2; hh++) {
                    float v = lm[mt][hh];
                    v = fmaxf(v, __shfl_xor_sync(0xffffffffu, v, 1));
                    v = fmaxf(v, __shfl_xor_sync(0xffffffffu, v, 2));
                    lm[mt][hh] = v;
                }
            if (t4 == 0) {
#pragma unroll
                for (int mt = 0; mt < 2; mt++)
#pragma unroll
                    for (int hh = 0; hh < 2; hh++)
                        red[wn * 128 + wm * 32 + mt * 16 + hh * 8 + g] = lm[mt][hh];
            }
            __syncthreads();
            if (tid < 128)
                scm[tid] = fmaxf(fmaxf(red[tid], red[128 + tid]),
                                 fmaxf(red[256 + tid], red[384 + tid]));
            __syncthreads();

            // ---- chunk sum of exp ----
            float ls[2][2];
#pragma unroll
            for (int mt = 0; mt < 2; mt++)
#pragma unroll
                for (int hh = 0; hh < 2; hh++) {
                    float cm = scm[wm * 32 + mt * 16 + hh * 8 + g];
                    float s = 0.f;
#pragma unroll
                    for (int nt = 0; nt < 8; nt++)
                        s += ex2sum2((d[mt][nt][2 * hh] - cm) * L2E,
                                     (d[mt][nt][2 * hh + 1] - cm) * L2E);
                    ls[mt][hh] = s;
                }
#pragma unroll
            for (int mt = 0; mt < 2; mt++)
#pragma unroll
                for (int hh = 0; hh < 2; hh++) {
                    float v = ls[mt][hh];
                    v += __shfl_xor_sync(0xffffffffu, v, 1);
                    v += __shfl_xor_sync(0xffffffffu, v, 2);
                    ls[mt][hh] = v;
                }
            if (t4 == 0) {
#pragma unroll
                for (int mt = 0; mt < 2; mt++)
#pragma unroll
                    for (int hh = 0; hh < 2; hh++)
                        red[wn * 128 + wm * 32 + mt * 16 + hh * 8 + g] = ls[mt][hh];
            }
            __syncthreads();
            if (tid < 128) {
                float cs = red[tid] + red[128 + tid] + red[256 + tid] + red[384 + tid];
                float mo = rmax[tid];
                float mn = fmaxf(mo, scm[tid]);
                rsum[tid] = rsum[tid] * exp2f((mo - mn) * L2E) +
                            cs * exp2f((scm[tid] - mn) * L2E);
                rmax[tid] = mn;
            }

            if (ch < 3) {
                // ---- stage f16 logits (streaming stores) + reset accums ----
#pragma unroll
                for (int mt = 0; mt < 2; mt++)
#pragma unroll
                    for (int hh = 0; hh < 2; hh++) {
                        size_t r = row0 + wm * 32 + mt * 16 + hh * 8 + g;
#pragma unroll
                        for (int nt = 0; nt < 8; nt++) {
                            int c = ch * 256 + wn * 64 + nt * 8 + t4 * 2;
                            __half2 hv = __floats2half2_rn(d[mt][nt][2 * hh],
                                                           d[mt][nt][2 * hh + 1]);
                            __stcs((__half2*)&g_logits[r * VV + c], hv);
                        }
                    }
#pragma unroll
                for (int mt = 0; mt < 2; mt++)
#pragma unroll
                    for (int nt = 0; nt < 8; nt++)
#pragma unroll
                        for (int q = 0; q < 4; q++) d[mt][nt][q] = 0.f;
            }
            // ch==3: keep biased logits in registers for direct output below
        }
    }

    // ---- finalize: rls ----
    __syncthreads();
    if (tid < 128) scm[tid] = logf(rsum[tid]) + rmax[tid];
    __syncthreads();

    // ---- chunk 3 output directly from registers ----
#pragma unroll
    for (int mt = 0; mt < 2; mt++)
#pragma unroll
        for (int hh = 0; hh < 2; hh++) {
            int rl = wm * 32 + mt * 16 + hh * 8 + g;
            float rls = scm[rl];
            size_t r = row0 + rl;
#pragma unroll
            for (int nt = 0; nt < 8; nt++) {
                int c = 768 + wn * 64 + nt * 8 + t4 * 2;
                float2 o;
                o.x = d[mt][nt][2 * hh] - rls;
                o.y = d[mt][nt][2 * hh + 1] - rls;
                __stcs((float2*)&out[r * VV + c], o);
            }
        }

    // ---- normalize staged chunks 0-2 (cols 0..767) ----
    for (int p = tid; p < 128 * 192; p += NTHR) {
        int r = p / 192;
        int c4 = p - r * 192;
        float rls = scm[r];
        uint2 lv = __ldcs((const uint2*)&g_logits[(row0 + r) * VV + c4 * 4]);
        float2 f0 = __half22float2(*(__half2*)&lv.x);
        float2 f1 = __half22float2(*(__half2*)&lv.y);
        float4 o;
        o.x = f0.x - rls;
        o.y = f0.y - rls;
        o.z = f1.x - rls;
        o.w = f1.y - rls;
        __stcs((float4*)&out[(row0 + r) * VV + c4 * 4], o);
    }
}

// ===========================================================================
extern "C" void kernel_launch(void* const* d_in, const int* in_sizes, int n_in,
                              void* d_out, int out_size) {
    const float* enc_out = (const float*)d_in[0];
    const float* pred_out = (const float*)d_in[1];
    const float* W_enc = (const float*)d_in[2];
    const float* b_enc = (const float*)d_in[3];
    const float* W_pred = (const float*)d_in[4];
    const float* b_pred = (const float*)d_in[5];
    const float* W_fc = (const float*)d_in[6];
    const float* b_fc = (const float*)d_in[7];
    float* out = (float*)d_out;

    cudaFuncSetAttribute(joint_gemm, cudaFuncAttributeMaxDynamicSharedMemorySize,
                         SM_TOTAL);

    proj_gemm<<<dim3((BB * TT) / 64, HH / 64, 5), 256>>>(enc_out, W_enc, 0);
    proj_gemm<<<dim3((BB * UU) / 64, HH / 64, 5), 256>>>(pred_out, W_pred, 1);
    reduce_convert<<<3200 + 640, 256>>>(b_enc, b_pred, W_fc);
    joint_gemm<<<MTOT / 128, NTHR, SM_TOTAL>>>(b_fc, out);
}